// round 1
// baseline (speedup 1.0000x reference)
#include <cuda_runtime.h>

#define NTOK   16384      // B*P*K*Hp*W = 2*8*4*16*16
#define CDIM   256
#define NHEADS 8
#define DK     32
#define SEQ    1024       // tokens per window
#define NWIN   16         // B*P

// Scratch (alloc-free): Q/K/V projections and attention context, token-major [NTOK][CDIM]
__device__ float g_q[NTOK * CDIM];
__device__ float g_k[NTOK * CDIM];
__device__ float g_v[NTOK * CDIM];
__device__ float g_ctx[NTOK * CDIM];

// ---------------------------------------------------------------------------
// Y[n][o] = sum_c X[n][c] * W[o][c] + b[o]
// BM=BN=64, BK=16, 256 threads, 4x4 per-thread tile.
// sel: 0/1/2 -> Y = g_q/g_k/g_v ; 3 -> X = g_ctx, Y = Yext
// ---------------------------------------------------------------------------
__global__ __launch_bounds__(256) void sgemm_nt_bias(
    const float* __restrict__ Xext, const float* __restrict__ W,
    const float* __restrict__ b, float* __restrict__ Yext, int sel)
{
    __shared__ float As[16][64];   // [k][row]
    __shared__ float Bs[16][64];   // [k][col]

    const float* X = (sel == 3) ? g_ctx : Xext;
    float* Y;
    if      (sel == 0) Y = g_q;
    else if (sel == 1) Y = g_k;
    else if (sel == 2) Y = g_v;
    else               Y = Yext;

    const int tid = threadIdx.x;
    const int tx  = tid & 15;
    const int ty  = tid >> 4;
    const int row0 = blockIdx.y * 64;
    const int col0 = blockIdx.x * 64;

    const int lr = tid >> 2;        // 0..63 : tile row
    const int lc = (tid & 3) * 4;   // 0,4,8,12 : k-offset

    float acc[4][4];
#pragma unroll
    for (int i = 0; i < 4; ++i)
#pragma unroll
        for (int j = 0; j < 4; ++j) acc[i][j] = 0.f;

    for (int k0 = 0; k0 < CDIM; k0 += 16) {
        float4 xa = *(const float4*)&X[(row0 + lr) * CDIM + k0 + lc];
        float4 wb = *(const float4*)&W[(col0 + lr) * CDIM + k0 + lc];
        As[lc + 0][lr] = xa.x; As[lc + 1][lr] = xa.y;
        As[lc + 2][lr] = xa.z; As[lc + 3][lr] = xa.w;
        Bs[lc + 0][lr] = wb.x; Bs[lc + 1][lr] = wb.y;
        Bs[lc + 2][lr] = wb.z; Bs[lc + 3][lr] = wb.w;
        __syncthreads();

#pragma unroll
        for (int kk = 0; kk < 16; ++kk) {
            float4 a4 = *(const float4*)&As[kk][ty * 4];
            float4 b4 = *(const float4*)&Bs[kk][tx * 4];
            float a[4] = {a4.x, a4.y, a4.z, a4.w};
            float bb[4] = {b4.x, b4.y, b4.z, b4.w};
#pragma unroll
            for (int i = 0; i < 4; ++i)
#pragma unroll
                for (int j = 0; j < 4; ++j)
                    acc[i][j] += a[i] * bb[j];
        }
        __syncthreads();
    }

    float4 bias = *(const float4*)&b[col0 + tx * 4];
#pragma unroll
    for (int i = 0; i < 4; ++i) {
        float4 r;
        r.x = acc[i][0] + bias.x;
        r.y = acc[i][1] + bias.y;
        r.z = acc[i][2] + bias.z;
        r.w = acc[i][3] + bias.w;
        *(float4*)&Y[(row0 + ty * 4 + i) * CDIM + col0 + tx * 4] = r;
    }
}

// ---------------------------------------------------------------------------
// Flash attention per (window, head, 64-row q-tile), dk=32, S=1024.
// 256 threads; scores: 4x4 register tiles over a 64x64 tile; online softmax;
// PV via P smem roundtrip, each thread accumulates O rows 4*ty..+4, cols 2*tx..+2.
// ---------------------------------------------------------------------------
__global__ __launch_bounds__(256) void attn_kernel()
{
    __shared__ float Qs[DK][64];     // [d][row]
    __shared__ float Ks[DK][64];     // [d][key]
    __shared__ float Vs[64][DK];     // [key][d]
    __shared__ float Ps[64][68];     // [row][key], padded

    const int tid = threadIdx.x;
    const int tx  = tid & 15;
    const int ty  = tid >> 4;
    const int qt  = blockIdx.x;      // 0..15
    const int h   = blockIdx.y;      // 0..7
    const int win = blockIdx.z;      // 0..15

    const float* qbase = g_q + (size_t)(win * SEQ + qt * 64) * CDIM + h * DK;
    const float* kbase = g_k + (size_t)(win * SEQ) * CDIM + h * DK;
    const float* vbase = g_v + (size_t)(win * SEQ) * CDIM + h * DK;

    // Load Q tile (64 x 32), transpose into Qs[d][row]
    {
        int t = tid;
#pragma unroll
        for (int it = 0; it < 2; ++it, t += 256) {
            int r  = t >> 3;
            int c4 = (t & 7) * 4;
            float4 v = *(const float4*)&qbase[r * CDIM + c4];
            Qs[c4 + 0][r] = v.x; Qs[c4 + 1][r] = v.y;
            Qs[c4 + 2][r] = v.z; Qs[c4 + 3][r] = v.w;
        }
    }

    float m[4], l[4], o[4][2];
#pragma unroll
    for (int i = 0; i < 4; ++i) {
        m[i] = -1e30f; l[i] = 0.f; o[i][0] = 0.f; o[i][1] = 0.f;
    }

    const float scale = 0.17677669529663687f;   // 1/sqrt(32)

    for (int kt = 0; kt < SEQ / 64; ++kt) {
        __syncthreads();   // prev-iter Ps/Vs reads done before overwrite
        {
            int t = tid;
#pragma unroll
            for (int it = 0; it < 2; ++it, t += 256) {
                int r  = t >> 3;
                int c4 = (t & 7) * 4;
                float4 kv = *(const float4*)&kbase[(kt * 64 + r) * CDIM + c4];
                Ks[c4 + 0][r] = kv.x; Ks[c4 + 1][r] = kv.y;
                Ks[c4 + 2][r] = kv.z; Ks[c4 + 3][r] = kv.w;
                float4 vv = *(const float4*)&vbase[(kt * 64 + r) * CDIM + c4];
                *(float4*)&Vs[r][c4] = vv;
            }
        }
        __syncthreads();

        // S = Q K^T on this 64x64 tile
        float s[4][4];
#pragma unroll
        for (int i = 0; i < 4; ++i)
#pragma unroll
            for (int j = 0; j < 4; ++j) s[i][j] = 0.f;

#pragma unroll
        for (int d = 0; d < DK; ++d) {
            float4 a4 = *(const float4*)&Qs[d][ty * 4];
            float4 b4 = *(const float4*)&Ks[d][tx * 4];
            float a[4] = {a4.x, a4.y, a4.z, a4.w};
            float bb[4] = {b4.x, b4.y, b4.z, b4.w};
#pragma unroll
            for (int i = 0; i < 4; ++i)
#pragma unroll
                for (int j = 0; j < 4; ++j)
                    s[i][j] += a[i] * bb[j];
        }

        // Online softmax per row (rows shared across the 16 tx-lanes of a half-warp)
#pragma unroll
        for (int i = 0; i < 4; ++i) {
#pragma unroll
            for (int j = 0; j < 4; ++j) s[i][j] *= scale;

            float mt = fmaxf(fmaxf(s[i][0], s[i][1]), fmaxf(s[i][2], s[i][3]));
#pragma unroll
            for (int w = 1; w < 16; w <<= 1)
                mt = fmaxf(mt, __shfl_xor_sync(0xffffffffu, mt, w));

            float mnew = fmaxf(m[i], mt);
            float corr = __expf(m[i] - mnew);
            float rs = 0.f;
#pragma unroll
            for (int j = 0; j < 4; ++j) {
                s[i][j] = __expf(s[i][j] - mnew);
                rs += s[i][j];
            }
#pragma unroll
            for (int w = 1; w < 16; w <<= 1)
                rs += __shfl_xor_sync(0xffffffffu, rs, w);

            l[i] = l[i] * corr + rs;
            m[i] = mnew;
            o[i][0] *= corr;
            o[i][1] *= corr;

            *(float4*)&Ps[ty * 4 + i][tx * 4] =
                make_float4(s[i][0], s[i][1], s[i][2], s[i][3]);
        }
        __syncthreads();

        // O += P @ V   (P: 64x64 in smem, V: 64x32 in smem)
#pragma unroll 8
        for (int k = 0; k < 64; ++k) {
            float2 vv = *(const float2*)&Vs[k][tx * 2];
#pragma unroll
            for (int i = 0; i < 4; ++i) {
                float p = Ps[ty * 4 + i][k];
                o[i][0] += p * vv.x;
                o[i][1] += p * vv.y;
            }
        }
    }

    float* obase = g_ctx + (size_t)(win * SEQ + qt * 64) * CDIM + h * DK;
#pragma unroll
    for (int i = 0; i < 4; ++i) {
        float inv = 1.f / l[i];
        float2 r = make_float2(o[i][0] * inv, o[i][1] * inv);
        *(float2*)&obase[(ty * 4 + i) * CDIM + tx * 2] = r;
    }
}

// ---------------------------------------------------------------------------
extern "C" void kernel_launch(void* const* d_in, const int* in_sizes, int n_in,
                              void* d_out, int out_size)
{
    const float* q  = (const float*)d_in[0];
    const float* k  = (const float*)d_in[1];
    const float* v  = (const float*)d_in[2];
    const float* Wq = (const float*)d_in[3];
    const float* bq = (const float*)d_in[4];
    const float* Wk = (const float*)d_in[5];
    const float* bk = (const float*)d_in[6];
    const float* Wv = (const float*)d_in[7];
    const float* bv = (const float*)d_in[8];
    const float* Wo = (const float*)d_in[9];
    const float* bo = (const float*)d_in[10];
    float* out = (float*)d_out;

    dim3 gblk(CDIM / 64, NTOK / 64);   // (4, 256)

    sgemm_nt_bias<<<gblk, 256>>>(q, Wq, bq, nullptr, 0);
    sgemm_nt_bias<<<gblk, 256>>>(k, Wk, bk, nullptr, 1);
    sgemm_nt_bias<<<gblk, 256>>>(v, Wv, bv, nullptr, 2);

    attn_kernel<<<dim3(SEQ / 64, NHEADS, NWIN), 256>>>();   // (16, 8, 16)

    sgemm_nt_bias<<<gblk, 256>>>(nullptr, Wo, bo, out, 3);
}

// round 3
// speedup vs baseline: 1.1894x; 1.1894x over previous
#include <cuda_runtime.h>
#include <cuda_bf16.h>
#include <cstdint>

#define NTOK   16384      // B*P*K*Hp*W
#define CDIM   256
#define NHEADS 8
#define DK     32
#define SEQ    1024
#define NWIN   16

// Scratch (alloc-free)
__device__ float g_q[NTOK * CDIM];
__device__ float g_k[NTOK * CDIM];
__device__ float g_v[NTOK * CDIM];
__device__ float g_ctx[NTOK * CDIM];

// ---------------------------------------------------------------------------
// helpers
// ---------------------------------------------------------------------------
__device__ __forceinline__ uint32_t smem_u32(const void* p) {
    uint32_t a;
    asm("{ .reg .u64 t; cvta.to.shared.u64 t, %1; cvt.u32.u64 %0, t; }"
        : "=r"(a) : "l"(p));
    return a;
}

__device__ __forceinline__ float ex2f(float x) {
    float y;
    asm("ex2.approx.ftz.f32 %0, %1;" : "=f"(y) : "f"(x));
    return y;
}

__device__ __forceinline__ void ldm_x4(uint32_t* r, uint32_t addr) {
    asm volatile("ldmatrix.sync.aligned.m8n8.x4.shared.b16 {%0,%1,%2,%3}, [%4];"
                 : "=r"(r[0]), "=r"(r[1]), "=r"(r[2]), "=r"(r[3]) : "r"(addr));
}

__device__ __forceinline__ void mma_bf16(float* d, const uint32_t* a,
                                         uint32_t b0, uint32_t b1) {
    asm volatile(
        "mma.sync.aligned.m16n8k16.row.col.f32.bf16.bf16.f32 "
        "{%0,%1,%2,%3}, {%4,%5,%6,%7}, {%8,%9}, {%0,%1,%2,%3};"
        : "+f"(d[0]), "+f"(d[1]), "+f"(d[2]), "+f"(d[3])
        : "r"(a[0]), "r"(a[1]), "r"(a[2]), "r"(a[3]), "r"(b0), "r"(b1));
}

// bf16 hi/lo split of a float4, packed as 2x uint32 (2 bf16 each)
__device__ __forceinline__ void split4(float4 v, uint2& hi, uint2& lo) {
    __nv_bfloat16 h0 = __float2bfloat16(v.x), h1 = __float2bfloat16(v.y);
    __nv_bfloat16 h2 = __float2bfloat16(v.z), h3 = __float2bfloat16(v.w);
    __nv_bfloat16 l0 = __float2bfloat16(v.x - __bfloat162float(h0));
    __nv_bfloat16 l1 = __float2bfloat16(v.y - __bfloat162float(h1));
    __nv_bfloat16 l2 = __float2bfloat16(v.z - __bfloat162float(h2));
    __nv_bfloat16 l3 = __float2bfloat16(v.w - __bfloat162float(h3));
    hi.x = (uint32_t)__bfloat16_as_ushort(h0) | ((uint32_t)__bfloat16_as_ushort(h1) << 16);
    hi.y = (uint32_t)__bfloat16_as_ushort(h2) | ((uint32_t)__bfloat16_as_ushort(h3) << 16);
    lo.x = (uint32_t)__bfloat16_as_ushort(l0) | ((uint32_t)__bfloat16_as_ushort(l1) << 16);
    lo.y = (uint32_t)__bfloat16_as_ushort(l2) | ((uint32_t)__bfloat16_as_ushort(l3) << 16);
}

// ---------------------------------------------------------------------------
// Projection via mma.sync bf16 hi/lo split (3-product fp32 emulation).
// Y[n][o] = sum_c X[n][c]*W[o][c] + b[o]
// Block: 256 threads (8 warps, 4Mx2N), tile 128(M)x128(N), K staged 64 at a time.
// ---------------------------------------------------------------------------
#define LDA 72                       // padded bf16 row length (144B, ldmatrix conflict-free)
#define SA_HI 0
#define SA_LO (128 * LDA)
#define SB_HI (2 * 128 * LDA)
#define SB_LO (3 * 128 * LDA)
#define PROJ_SMEM (4 * 128 * LDA * 2)   // bytes = 73728

__global__ void __launch_bounds__(256, 1)
proj_mma(const float* __restrict__ Xext, const float* __restrict__ W,
         const float* __restrict__ bias, float* __restrict__ Yext, int sel)
{
    extern __shared__ __nv_bfloat16 sb[];

    const float* X = (sel == 3) ? g_ctx : Xext;
    float* Y;
    if      (sel == 0) Y = g_q;
    else if (sel == 1) Y = g_k;
    else if (sel == 2) Y = g_v;
    else               Y = Yext;

    const int tid = threadIdx.x;
    const int l   = tid & 31;
    const int wid = tid >> 5;
    const int wm  = wid & 3;        // warp M index (0..3) -> rows wm*32..+32
    const int wn  = wid >> 2;       // warp N index (0..1) -> cols wn*64..+64
    const int row0 = blockIdx.y * 128;
    const int col0 = blockIdx.x * 128;

    float acc[2][8][4];
#pragma unroll
    for (int m = 0; m < 2; ++m)
#pragma unroll
        for (int n = 0; n < 8; ++n)
#pragma unroll
            for (int i = 0; i < 4; ++i) acc[m][n][i] = 0.f;

    // precompute ldmatrix smem addresses (element offsets -> byte addrs)
    const uint32_t a_off_elem =
        (uint32_t)(wm * 32 + (l & 15)) * LDA + ((l >> 4) * 8);
    const uint32_t b_off_elem =
        (uint32_t)(wn * 64 + (l & 7) + ((l >> 4) << 3)) * LDA + (((l >> 3) & 1) * 8);
    const uint32_t smb = smem_u32(sb);

    for (int kb = 0; kb < 4; ++kb) {
        // stage K-block of 64: split X and W rows into bf16 hi/lo
#pragma unroll
        for (int i = 0; i < 8; ++i) {
            int t   = tid + i * 256;        // 0..2047
            int row = t >> 4;               // 0..127
            int c4  = (t & 15) * 4;         // 0..60
            uint2 hi, lo;
            split4(*(const float4*)&X[(size_t)(row0 + row) * CDIM + kb * 64 + c4], hi, lo);
            *(uint2*)&sb[SA_HI + row * LDA + c4] = hi;
            *(uint2*)&sb[SA_LO + row * LDA + c4] = lo;
            split4(*(const float4*)&W[(size_t)(col0 + row) * CDIM + kb * 64 + c4], hi, lo);
            *(uint2*)&sb[SB_HI + row * LDA + c4] = hi;
            *(uint2*)&sb[SB_LO + row * LDA + c4] = lo;
        }
        __syncthreads();

#pragma unroll
        for (int ks = 0; ks < 4; ++ks) {
            const uint32_t kk = ks * 16;
            uint32_t ahi[2][4], alo[2][4];
#pragma unroll
            for (int m = 0; m < 2; ++m) {
                uint32_t ae = a_off_elem + (uint32_t)m * 16 * LDA + kk;
                ldm_x4(ahi[m], smb + (SA_HI + ae) * 2);
                ldm_x4(alo[m], smb + (SA_LO + ae) * 2);
            }
#pragma unroll
            for (int p = 0; p < 4; ++p) {
                uint32_t be = b_off_elem + (uint32_t)p * 16 * LDA + kk;
                uint32_t bhi[4], blo[4];
                ldm_x4(bhi, smb + (SB_HI + be) * 2);
                ldm_x4(blo, smb + (SB_LO + be) * 2);
#pragma unroll
                for (int m = 0; m < 2; ++m) {
                    mma_bf16(acc[m][2 * p + 0], ahi[m], bhi[0], bhi[1]);
                    mma_bf16(acc[m][2 * p + 0], ahi[m], blo[0], blo[1]);
                    mma_bf16(acc[m][2 * p + 0], alo[m], bhi[0], bhi[1]);
                    mma_bf16(acc[m][2 * p + 1], ahi[m], bhi[2], bhi[3]);
                    mma_bf16(acc[m][2 * p + 1], ahi[m], blo[2], blo[3]);
                    mma_bf16(acc[m][2 * p + 1], alo[m], bhi[2], bhi[3]);
                }
            }
        }
        __syncthreads();
    }

    // epilogue: d0,d1 -> (row, col..col+1); d2,d3 -> (row+8, ...)
#pragma unroll
    for (int m = 0; m < 2; ++m) {
        int r = row0 + wm * 32 + m * 16 + (l >> 2);
#pragma unroll
        for (int n = 0; n < 8; ++n) {
            int c = col0 + wn * 64 + n * 8 + (l & 3) * 2;
            float2 b2 = *(const float2*)&bias[c];
            *(float2*)&Y[(size_t)r * CDIM + c] =
                make_float2(acc[m][n][0] + b2.x, acc[m][n][1] + b2.y);
            *(float2*)&Y[(size_t)(r + 8) * CDIM + c] =
                make_float2(acc[m][n][2] + b2.x, acc[m][n][3] + b2.y);
        }
    }
}

// ---------------------------------------------------------------------------
// Flash attention per (window, head, 64-row q-tile), dk=32, S=1024, fp32.
// V transposed as float2 pairs (vectorized PV), log2-domain softmax (ex2).
// ---------------------------------------------------------------------------
__global__ __launch_bounds__(256) void attn_kernel()
{
    __shared__ float  Qs[DK][64];       // [d][row]
    __shared__ float  Ks[DK][64];       // [d][key]
    __shared__ float2 Vp[16][66];       // [d_pair][key]
    __shared__ float  Ps[64][68];       // [row][key]

    const int tid = threadIdx.x;
    const int tx  = tid & 15;
    const int ty  = tid >> 4;
    const int qt  = blockIdx.x;
    const int h   = blockIdx.y;
    const int win = blockIdx.z;

    const float* qbase = g_q + (size_t)(win * SEQ + qt * 64) * CDIM + h * DK;
    const float* kbase = g_k + (size_t)(win * SEQ) * CDIM + h * DK;
    const float* vbase = g_v + (size_t)(win * SEQ) * CDIM + h * DK;

    {
        int t = tid;
#pragma unroll
        for (int it = 0; it < 2; ++it, t += 256) {
            int r  = t >> 3;
            int c4 = (t & 7) * 4;
            float4 v = *(const float4*)&qbase[r * CDIM + c4];
            Qs[c4 + 0][r] = v.x; Qs[c4 + 1][r] = v.y;
            Qs[c4 + 2][r] = v.z; Qs[c4 + 3][r] = v.w;
        }
    }

    float m[4], l[4], o[4][2];
#pragma unroll
    for (int i = 0; i < 4; ++i) {
        m[i] = -1e30f; l[i] = 0.f; o[i][0] = 0.f; o[i][1] = 0.f;
    }

    const float qscale = 0.17677669529663687f * 1.4426950408889634f;  // 1/sqrt(32)*log2e

    for (int kt = 0; kt < SEQ / 64; ++kt) {
        __syncthreads();
        {
            int t = tid;
#pragma unroll
            for (int it = 0; it < 2; ++it, t += 256) {
                int r  = t >> 3;
                int c4 = (t & 7) * 4;
                float4 kv = *(const float4*)&kbase[(kt * 64 + r) * CDIM + c4];
                Ks[c4 + 0][r] = kv.x; Ks[c4 + 1][r] = kv.y;
                Ks[c4 + 2][r] = kv.z; Ks[c4 + 3][r] = kv.w;
                float4 vv = *(const float4*)&vbase[(kt * 64 + r) * CDIM + c4];
                Vp[(c4 >> 1) + 0][r] = make_float2(vv.x, vv.y);
                Vp[(c4 >> 1) + 1][r] = make_float2(vv.z, vv.w);
            }
        }
        __syncthreads();

        float s[4][4];
#pragma unroll
        for (int i = 0; i < 4; ++i)
#pragma unroll
            for (int j = 0; j < 4; ++j) s[i][j] = 0.f;

#pragma unroll
        for (int d = 0; d < DK; ++d) {
            float4 a4 = *(const float4*)&Qs[d][ty * 4];
            float4 b4 = *(const float4*)&Ks[d][tx * 4];
            float a[4] = {a4.x, a4.y, a4.z, a4.w};
            float bb[4] = {b4.x, b4.y, b4.z, b4.w};
#pragma unroll
            for (int i = 0; i < 4; ++i)
#pragma unroll
                for (int j = 0; j < 4; ++j)
                    s[i][j] += a[i] * bb[j];
        }

#pragma unroll
        for (int i = 0; i < 4; ++i) {
#pragma unroll
            for (int j = 0; j < 4; ++j) s[i][j] *= qscale;

            float mt = fmaxf(fmaxf(s[i][0], s[i][1]), fmaxf(s[i][2], s[i][3]));
#pragma unroll
            for (int w = 1; w < 16; w <<= 1)
                mt = fmaxf(mt, __shfl_xor_sync(0xffffffffu, mt, w));

            float mnew = fmaxf(m[i], mt);
            float corr = ex2f(m[i] - mnew);
            float rs = 0.f;
#pragma unroll
            for (int j = 0; j < 4; ++j) {
                s[i][j] = ex2f(s[i][j] - mnew);
                rs += s[i][j];
            }
#pragma unroll
            for (int w = 1; w < 16; w <<= 1)
                rs += __shfl_xor_sync(0xffffffffu, rs, w);

            l[i] = l[i] * corr + rs;
            m[i] = mnew;
            o[i][0] *= corr;
            o[i][1] *= corr;

            *(float4*)&Ps[ty * 4 + i][tx * 4] =
                make_float4(s[i][0], s[i][1], s[i][2], s[i][3]);
        }
        __syncthreads();

#pragma unroll
        for (int k0 = 0; k0 < 64; k0 += 4) {
            float4 va = *(const float4*)&Vp[tx][k0];
            float4 vb = *(const float4*)&Vp[tx][k0 + 2];
#pragma unroll
            for (int i = 0; i < 4; ++i) {
                float4 p = *(const float4*)&Ps[ty * 4 + i][k0];
                o[i][0] += p.x * va.x + p.y * va.z + p.z * vb.x + p.w * vb.z;
                o[i][1] += p.x * va.y + p.y * va.w + p.z * vb.y + p.w * vb.w;
            }
        }
    }

    float* obase = g_ctx + (size_t)(win * SEQ + qt * 64) * CDIM + h * DK;
#pragma unroll
    for (int i = 0; i < 4; ++i) {
        float inv = 1.f / l[i];
        *(float2*)&obase[(ty * 4 + i) * CDIM + tx * 2] =
            make_float2(o[i][0] * inv, o[i][1] * inv);
    }
}

// ---------------------------------------------------------------------------
extern "C" void kernel_launch(void* const* d_in, const int* in_sizes, int n_in,
                              void* d_out, int out_size)
{
    const float* q  = (const float*)d_in[0];
    const float* k  = (const float*)d_in[1];
    const float* v  = (const float*)d_in[2];
    const float* Wq = (const float*)d_in[3];
    const float* bq = (const float*)d_in[4];
    const float* Wk = (const float*)d_in[5];
    const float* bk = (const float*)d_in[6];
    const float* Wv = (const float*)d_in[7];
    const float* bv = (const float*)d_in[8];
    const float* Wo = (const float*)d_in[9];
    const float* bo = (const float*)d_in[10];
    float* out = (float*)d_out;

    cudaFuncSetAttribute(proj_mma,
                         cudaFuncAttributeMaxDynamicSharedMemorySize, PROJ_SMEM);

    dim3 pgrid(CDIM / 128, NTOK / 128);   // (2, 128)

    proj_mma<<<pgrid, 256, PROJ_SMEM>>>(q, Wq, bq, nullptr, 0);
    proj_mma<<<pgrid, 256, PROJ_SMEM>>>(k, Wk, bk, nullptr, 1);
    proj_mma<<<pgrid, 256, PROJ_SMEM>>>(v, Wv, bv, nullptr, 2);

    attn_kernel<<<dim3(SEQ / 64, NHEADS, NWIN), 256>>>();

    proj_mma<<<pgrid, 256, PROJ_SMEM>>>(nullptr, Wo, bo, out, 3);
}

// round 4
// speedup vs baseline: 2.6165x; 2.1998x over previous
#include <cuda_runtime.h>
#include <cuda_bf16.h>
#include <cstdint>

#define NTOK   16384      // B*P*K*Hp*W
#define CDIM   256
#define NHEADS 8
#define DK     32
#define SEQ    1024
#define NWIN   16

// Scratch (alloc-free)
__device__ float g_q[NTOK * CDIM];
__device__ float g_k[NTOK * CDIM];
__device__ float g_v[NTOK * CDIM];
__device__ float g_ctx[NTOK * CDIM];

// ---------------------------------------------------------------------------
// helpers
// ---------------------------------------------------------------------------
__device__ __forceinline__ uint32_t smem_u32(const void* p) {
    uint32_t a;
    asm("{ .reg .u64 t; cvta.to.shared.u64 t, %1; cvt.u32.u64 %0, t; }"
        : "=r"(a) : "l"(p));
    return a;
}

__device__ __forceinline__ float ex2f(float x) {
    float y;
    asm("ex2.approx.ftz.f32 %0, %1;" : "=f"(y) : "f"(x));
    return y;
}

__device__ __forceinline__ void ldm_x4(uint32_t* r, uint32_t addr) {
    asm volatile("ldmatrix.sync.aligned.m8n8.x4.shared.b16 {%0,%1,%2,%3}, [%4];"
                 : "=r"(r[0]), "=r"(r[1]), "=r"(r[2]), "=r"(r[3]) : "r"(addr));
}

__device__ __forceinline__ void mma_bf16(float* d, const uint32_t* a,
                                         uint32_t b0, uint32_t b1) {
    asm volatile(
        "mma.sync.aligned.m16n8k16.row.col.f32.bf16.bf16.f32 "
        "{%0,%1,%2,%3}, {%4,%5,%6,%7}, {%8,%9}, {%0,%1,%2,%3};"
        : "+f"(d[0]), "+f"(d[1]), "+f"(d[2]), "+f"(d[3])
        : "r"(a[0]), "r"(a[1]), "r"(a[2]), "r"(a[3]), "r"(b0), "r"(b1));
}

// pack (a -> low half, b -> high half) as bf16x2
__device__ __forceinline__ uint32_t bfpair(float a, float b) {
    uint32_t r;
    asm("cvt.rn.bf16x2.f32 %0, %1, %2;" : "=r"(r) : "f"(b), "f"(a));
    return r;
}

// hi/lo bf16 split of a float pair
__device__ __forceinline__ void split_pair(float a, float b,
                                           uint32_t& hi, uint32_t& lo) {
    hi = bfpair(a, b);
    float ah = __uint_as_float(hi << 16);
    float bh = __uint_as_float(hi & 0xFFFF0000u);
    lo = bfpair(a - ah, b - bh);
}

// bf16 hi/lo split of a float4, packed as 2x uint32 (2 bf16 each)
__device__ __forceinline__ void split4(float4 v, uint2& hi, uint2& lo) {
    split_pair(v.x, v.y, hi.x, lo.x);
    split_pair(v.z, v.w, hi.y, lo.y);
}

// ---------------------------------------------------------------------------
// Projection via mma.sync bf16 hi/lo split (3-product fp32 emulation).
// (unchanged from R3 — verified)
// ---------------------------------------------------------------------------
#define LDA 72
#define SA_HI 0
#define SA_LO (128 * LDA)
#define SB_HI (2 * 128 * LDA)
#define SB_LO (3 * 128 * LDA)
#define PROJ_SMEM (4 * 128 * LDA * 2)

__global__ void __launch_bounds__(256, 1)
proj_mma(const float* __restrict__ Xext, const float* __restrict__ W,
         const float* __restrict__ bias, float* __restrict__ Yext, int sel)
{
    extern __shared__ __nv_bfloat16 sb[];

    const float* X = (sel == 3) ? g_ctx : Xext;
    float* Y;
    if      (sel == 0) Y = g_q;
    else if (sel == 1) Y = g_k;
    else if (sel == 2) Y = g_v;
    else               Y = Yext;

    const int tid = threadIdx.x;
    const int l   = tid & 31;
    const int wid = tid >> 5;
    const int wm  = wid & 3;
    const int wn  = wid >> 2;
    const int row0 = blockIdx.y * 128;
    const int col0 = blockIdx.x * 128;

    float acc[2][8][4];
#pragma unroll
    for (int m = 0; m < 2; ++m)
#pragma unroll
        for (int n = 0; n < 8; ++n)
#pragma unroll
            for (int i = 0; i < 4; ++i) acc[m][n][i] = 0.f;

    const uint32_t a_off_elem =
        (uint32_t)(wm * 32 + (l & 15)) * LDA + ((l >> 4) * 8);
    const uint32_t b_off_elem =
        (uint32_t)(wn * 64 + (l & 7) + ((l >> 4) << 3)) * LDA + (((l >> 3) & 1) * 8);
    const uint32_t smb = smem_u32(sb);

    for (int kb = 0; kb < 4; ++kb) {
#pragma unroll
        for (int i = 0; i < 8; ++i) {
            int t   = tid + i * 256;
            int row = t >> 4;
            int c4  = (t & 15) * 4;
            uint2 hi, lo;
            split4(*(const float4*)&X[(size_t)(row0 + row) * CDIM + kb * 64 + c4], hi, lo);
            *(uint2*)&sb[SA_HI + row * LDA + c4] = hi;
            *(uint2*)&sb[SA_LO + row * LDA + c4] = lo;
            split4(*(const float4*)&W[(size_t)(col0 + row) * CDIM + kb * 64 + c4], hi, lo);
            *(uint2*)&sb[SB_HI + row * LDA + c4] = hi;
            *(uint2*)&sb[SB_LO + row * LDA + c4] = lo;
        }
        __syncthreads();

#pragma unroll
        for (int ks = 0; ks < 4; ++ks) {
            const uint32_t kk = ks * 16;
            uint32_t ahi[2][4], alo[2][4];
#pragma unroll
            for (int m = 0; m < 2; ++m) {
                uint32_t ae = a_off_elem + (uint32_t)m * 16 * LDA + kk;
                ldm_x4(ahi[m], smb + (SA_HI + ae) * 2);
                ldm_x4(alo[m], smb + (SA_LO + ae) * 2);
            }
#pragma unroll
            for (int p = 0; p < 4; ++p) {
                uint32_t be = b_off_elem + (uint32_t)p * 16 * LDA + kk;
                uint32_t bhi[4], blo[4];
                ldm_x4(bhi, smb + (SB_HI + be) * 2);
                ldm_x4(blo, smb + (SB_LO + be) * 2);
#pragma unroll
                for (int m = 0; m < 2; ++m) {
                    mma_bf16(acc[m][2 * p + 0], ahi[m], bhi[0], bhi[1]);
                    mma_bf16(acc[m][2 * p + 0], ahi[m], blo[0], blo[1]);
                    mma_bf16(acc[m][2 * p + 0], alo[m], bhi[0], bhi[1]);
                    mma_bf16(acc[m][2 * p + 1], ahi[m], bhi[2], bhi[3]);
                    mma_bf16(acc[m][2 * p + 1], ahi[m], blo[2], blo[3]);
                    mma_bf16(acc[m][2 * p + 1], alo[m], bhi[2], bhi[3]);
                }
            }
        }
        __syncthreads();
    }

#pragma unroll
    for (int m = 0; m < 2; ++m) {
        int r = row0 + wm * 32 + m * 16 + (l >> 2);
#pragma unroll
        for (int n = 0; n < 8; ++n) {
            int c = col0 + wn * 64 + n * 8 + (l & 3) * 2;
            float2 b2 = *(const float2*)&bias[c];
            *(float2*)&Y[(size_t)r * CDIM + c] =
                make_float2(acc[m][n][0] + b2.x, acc[m][n][1] + b2.y);
            *(float2*)&Y[(size_t)(r + 8) * CDIM + c] =
                make_float2(acc[m][n][2] + b2.x, acc[m][n][3] + b2.y);
        }
    }
}

// ---------------------------------------------------------------------------
// Flash attention on mma.sync bf16 hi/lo splits.
// Block = 256 thr (8 warps x 16 q-rows = 128 q-rows), one (win, head).
// K-tiles of 64 keys. S acc in registers; P repacked in-register to A frags.
// ---------------------------------------------------------------------------
#define LDQ 40      // Q/K row pad (elems): 80B stride, conflict-free ldmatrix
#define LDV 72      // Vt row pad: 144B stride, conflict-free

__global__ void __launch_bounds__(256, 2) attn_mma()
{
    __shared__ __nv_bfloat16 sQh[128 * LDQ];
    __shared__ __nv_bfloat16 sQl[128 * LDQ];
    __shared__ __nv_bfloat16 sKh[64 * LDQ];
    __shared__ __nv_bfloat16 sKl[64 * LDQ];
    __shared__ __nv_bfloat16 sVh[32 * LDV];   // transposed: [d][key]
    __shared__ __nv_bfloat16 sVl[32 * LDV];

    const int tid = threadIdx.x;
    const int l   = tid & 31;
    const int wm  = tid >> 5;        // warp id 0..7 -> q rows wm*16..+16
    const int qt  = blockIdx.x;      // 0..7
    const int h   = blockIdx.y;      // 0..7
    const int win = blockIdx.z;      // 0..15

    const float qscale = 0.17677669529663687f * 1.4426950408889634f;

    // ---- stage Q (scaled), split hi/lo ----
    {
        int row = tid >> 1;
        int dg  = (tid & 1) * 16;
        const float* src = g_q + (size_t)(win * SEQ + qt * 128 + row) * CDIM + h * DK + dg;
#pragma unroll
        for (int i = 0; i < 4; ++i) {
            float4 v = *(const float4*)&src[i * 4];
            v.x *= qscale; v.y *= qscale; v.z *= qscale; v.w *= qscale;
            uint2 hi, lo;
            split4(v, hi, lo);
            *(uint2*)&sQh[row * LDQ + dg + i * 4] = hi;
            *(uint2*)&sQl[row * LDQ + dg + i * 4] = lo;
        }
    }
    __syncthreads();

    // ---- preload Q fragments (fixed for all key tiles) ----
    uint32_t qh[2][4], ql[2][4];
    {
        const uint32_t qb = smem_u32(sQh);
        const uint32_t qlb = smem_u32(sQl);
        uint32_t off = ((uint32_t)(wm * 16 + (l & 15)) * LDQ + (l >> 4) * 8) * 2;
#pragma unroll
        for (int kk = 0; kk < 2; ++kk) {
            ldm_x4(qh[kk], qb + off + kk * 32);
            ldm_x4(ql[kk], qlb + off + kk * 32);
        }
    }

    // ldmatrix base offsets for K (B operand) and Vt (B operand)
    const uint32_t kb_hi = smem_u32(sKh);
    const uint32_t kb_lo = smem_u32(sKl);
    const uint32_t vb_hi = smem_u32(sVh);
    const uint32_t vb_lo = smem_u32(sVl);
    const uint32_t k_lane = ((uint32_t)((l & 7) + ((l >> 4) << 3)) * LDQ +
                            ((l >> 3) & 1) * 8) * 2;
    const uint32_t v_lane = ((uint32_t)((l & 7) + ((l >> 4) << 3)) * LDV +
                            ((l >> 3) & 1) * 8) * 2;

    float m0 = -1e30f, m1 = -1e30f, l0 = 0.f, l1 = 0.f;
    float o[4][4];
#pragma unroll
    for (int n = 0; n < 4; ++n)
#pragma unroll
        for (int i = 0; i < 4; ++i) o[n][i] = 0.f;

    const float* kbase = g_k + (size_t)(win * SEQ) * CDIM + h * DK;
    const float* vbase = g_v + (size_t)(win * SEQ) * CDIM + h * DK;

    for (int kt = 0; kt < SEQ / 64; ++kt) {
        if (kt) __syncthreads();
        // ---- stage K tile (64 x 32) hi/lo ----
        {
            int key = tid & 63;
            int dg  = (tid >> 6) * 8;
            const float* src = kbase + (size_t)(kt * 64 + key) * CDIM + dg;
#pragma unroll
            for (int i = 0; i < 2; ++i) {
                uint2 hi, lo;
                split4(*(const float4*)&src[i * 4], hi, lo);
                *(uint2*)&sKh[key * LDQ + dg + i * 4] = hi;
                *(uint2*)&sKl[key * LDQ + dg + i * 4] = lo;
            }
        }
        // ---- stage V tile transposed: sV[d][key] ----
        {
            int key = tid & 63;
            int dg  = (tid >> 6) * 8;
            const float* src = vbase + (size_t)(kt * 64 + key) * CDIM + dg;
#pragma unroll
            for (int i = 0; i < 2; ++i) {
                float4 v = *(const float4*)&src[i * 4];
                float vv[4] = {v.x, v.y, v.z, v.w};
#pragma unroll
                for (int e = 0; e < 4; ++e) {
                    int d = dg + i * 4 + e;
                    __nv_bfloat16 hb = __float2bfloat16(vv[e]);
                    float hf = __bfloat162float(hb);
                    sVh[d * LDV + key] = hb;
                    sVl[d * LDV + key] = __float2bfloat16(vv[e] - hf);
                }
            }
        }
        __syncthreads();

        // ---- S = Q K^T (16 x 64 per warp), 3-product split ----
        float s[8][4];
#pragma unroll
        for (int j = 0; j < 8; ++j)
#pragma unroll
            for (int i = 0; i < 4; ++i) s[j][i] = 0.f;

#pragma unroll
        for (int kk = 0; kk < 2; ++kk) {
#pragma unroll
            for (int jp = 0; jp < 4; ++jp) {
                uint32_t koff = k_lane + ((uint32_t)(jp * 16 * LDQ + kk * 16)) * 2;
                uint32_t kh[4], kl[4];
                ldm_x4(kh, kb_hi + koff);
                ldm_x4(kl, kb_lo + koff);
                mma_bf16(s[2 * jp + 0], qh[kk], kh[0], kh[1]);
                mma_bf16(s[2 * jp + 0], qh[kk], kl[0], kl[1]);
                mma_bf16(s[2 * jp + 0], ql[kk], kh[0], kh[1]);
                mma_bf16(s[2 * jp + 1], qh[kk], kh[2], kh[3]);
                mma_bf16(s[2 * jp + 1], qh[kk], kl[2], kl[3]);
                mma_bf16(s[2 * jp + 1], ql[kk], kh[2], kh[3]);
            }
        }

        // ---- online softmax (rows r=l>>2 and r+8; quad reduction) ----
        float mx0 = -1e30f, mx1 = -1e30f;
#pragma unroll
        for (int j = 0; j < 8; ++j) {
            mx0 = fmaxf(mx0, fmaxf(s[j][0], s[j][1]));
            mx1 = fmaxf(mx1, fmaxf(s[j][2], s[j][3]));
        }
        mx0 = fmaxf(mx0, __shfl_xor_sync(0xffffffffu, mx0, 1));
        mx0 = fmaxf(mx0, __shfl_xor_sync(0xffffffffu, mx0, 2));
        mx1 = fmaxf(mx1, __shfl_xor_sync(0xffffffffu, mx1, 1));
        mx1 = fmaxf(mx1, __shfl_xor_sync(0xffffffffu, mx1, 2));

        float mn0 = fmaxf(m0, mx0), mn1 = fmaxf(m1, mx1);
        float c0 = ex2f(m0 - mn0), c1 = ex2f(m1 - mn1);
        m0 = mn0; m1 = mn1;

        float rs0 = 0.f, rs1 = 0.f;
#pragma unroll
        for (int j = 0; j < 8; ++j) {
            s[j][0] = ex2f(s[j][0] - mn0);
            s[j][1] = ex2f(s[j][1] - mn0);
            s[j][2] = ex2f(s[j][2] - mn1);
            s[j][3] = ex2f(s[j][3] - mn1);
            rs0 += s[j][0] + s[j][1];
            rs1 += s[j][2] + s[j][3];
        }
        rs0 += __shfl_xor_sync(0xffffffffu, rs0, 1);
        rs0 += __shfl_xor_sync(0xffffffffu, rs0, 2);
        rs1 += __shfl_xor_sync(0xffffffffu, rs1, 1);
        rs1 += __shfl_xor_sync(0xffffffffu, rs1, 2);

        l0 = l0 * c0 + rs0;
        l1 = l1 * c1 + rs1;
#pragma unroll
        for (int n = 0; n < 4; ++n) {
            o[n][0] *= c0; o[n][1] *= c0;
            o[n][2] *= c1; o[n][3] *= c1;
        }

        // ---- O += P V : repack S acc -> A frags (hi/lo), B from Vt ----
#pragma unroll
        for (int kc = 0; kc < 4; ++kc) {
            uint32_t ph[4], pl[4];
            split_pair(s[2 * kc][0],     s[2 * kc][1],     ph[0], pl[0]);
            split_pair(s[2 * kc][2],     s[2 * kc][3],     ph[1], pl[1]);
            split_pair(s[2 * kc + 1][0], s[2 * kc + 1][1], ph[2], pl[2]);
            split_pair(s[2 * kc + 1][2], s[2 * kc + 1][3], ph[3], pl[3]);
#pragma unroll
            for (int np = 0; np < 2; ++np) {
                uint32_t voff = v_lane + ((uint32_t)(np * 16 * LDV + kc * 16)) * 2;
                uint32_t vh[4], vl[4];
                ldm_x4(vh, vb_hi + voff);
                ldm_x4(vl, vb_lo + voff);
                mma_bf16(o[2 * np + 0], ph, vh[0], vh[1]);
                mma_bf16(o[2 * np + 0], ph, vl[0], vl[1]);
                mma_bf16(o[2 * np + 0], pl, vh[0], vh[1]);
                mma_bf16(o[2 * np + 1], ph, vh[2], vh[3]);
                mma_bf16(o[2 * np + 1], ph, vl[2], vl[3]);
                mma_bf16(o[2 * np + 1], pl, vh[2], vh[3]);
            }
        }
    }

    // ---- epilogue: normalize by l, write ctx ----
    float inv0 = 1.f / l0, inv1 = 1.f / l1;
    int r_lo = win * SEQ + qt * 128 + wm * 16 + (l >> 2);
    int col  = h * DK + (l & 3) * 2;
#pragma unroll
    for (int n = 0; n < 4; ++n) {
        int c = col + n * 8;
        *(float2*)&g_ctx[(size_t)r_lo * CDIM + c] =
            make_float2(o[n][0] * inv0, o[n][1] * inv0);
        *(float2*)&g_ctx[(size_t)(r_lo + 8) * CDIM + c] =
            make_float2(o[n][2] * inv1, o[n][3] * inv1);
    }
}

// ---------------------------------------------------------------------------
extern "C" void kernel_launch(void* const* d_in, const int* in_sizes, int n_in,
                              void* d_out, int out_size)
{
    const float* q  = (const float*)d_in[0];
    const float* k  = (const float*)d_in[1];
    const float* v  = (const float*)d_in[2];
    const float* Wq = (const float*)d_in[3];
    const float* bq = (const float*)d_in[4];
    const float* Wk = (const float*)d_in[5];
    const float* bk = (const float*)d_in[6];
    const float* Wv = (const float*)d_in[7];
    const float* bv = (const float*)d_in[8];
    const float* Wo = (const float*)d_in[9];
    const float* bo = (const float*)d_in[10];
    float* out = (float*)d_out;

    cudaFuncSetAttribute(proj_mma,
                         cudaFuncAttributeMaxDynamicSharedMemorySize, PROJ_SMEM);

    dim3 pgrid(CDIM / 128, NTOK / 128);

    proj_mma<<<pgrid, 256, PROJ_SMEM>>>(q, Wq, bq, nullptr, 0);
    proj_mma<<<pgrid, 256, PROJ_SMEM>>>(k, Wk, bk, nullptr, 1);
    proj_mma<<<pgrid, 256, PROJ_SMEM>>>(v, Wv, bv, nullptr, 2);

    attn_mma<<<dim3(SEQ / 128, NHEADS, NWIN), 256>>>();   // (8, 8, 16)

    proj_mma<<<pgrid, 256, PROJ_SMEM>>>(nullptr, Wo, bo, out, 3);
}

// round 5
// speedup vs baseline: 3.1329x; 1.1974x over previous
#include <cuda_runtime.h>
#include <cuda_bf16.h>
#include <cstdint>

#define NTOK   16384      // B*P*K*Hp*W
#define CDIM   256
#define NHEADS 8
#define DK     32
#define SEQ    1024
#define NWIN   16

#define QSCALE (0.17677669529663687f * 1.4426950408889634f)  // 1/sqrt(32)*log2e

// Scratch (alloc-free): pre-split bf16 hi/lo Q/K/V, fp32 ctx
__device__ __nv_bfloat16 g_qh[NTOK * CDIM];
__device__ __nv_bfloat16 g_ql[NTOK * CDIM];
__device__ __nv_bfloat16 g_kh[NTOK * CDIM];
__device__ __nv_bfloat16 g_kl[NTOK * CDIM];
__device__ __nv_bfloat16 g_vh[NTOK * CDIM];
__device__ __nv_bfloat16 g_vl[NTOK * CDIM];
__device__ float g_ctx[NTOK * CDIM];

// ---------------------------------------------------------------------------
// helpers
// ---------------------------------------------------------------------------
__device__ __forceinline__ uint32_t smem_u32(const void* p) {
    uint32_t a;
    asm("{ .reg .u64 t; cvta.to.shared.u64 t, %1; cvt.u32.u64 %0, t; }"
        : "=r"(a) : "l"(p));
    return a;
}

__device__ __forceinline__ float ex2f(float x) {
    float y;
    asm("ex2.approx.ftz.f32 %0, %1;" : "=f"(y) : "f"(x));
    return y;
}

__device__ __forceinline__ void ldm_x4(uint32_t* r, uint32_t addr) {
    asm volatile("ldmatrix.sync.aligned.m8n8.x4.shared.b16 {%0,%1,%2,%3}, [%4];"
                 : "=r"(r[0]), "=r"(r[1]), "=r"(r[2]), "=r"(r[3]) : "r"(addr));
}

__device__ __forceinline__ void ldm_x4t(uint32_t* r, uint32_t addr) {
    asm volatile("ldmatrix.sync.aligned.m8n8.x4.trans.shared.b16 {%0,%1,%2,%3}, [%4];"
                 : "=r"(r[0]), "=r"(r[1]), "=r"(r[2]), "=r"(r[3]) : "r"(addr));
}

__device__ __forceinline__ void mma_bf16(float* d, const uint32_t* a,
                                         uint32_t b0, uint32_t b1) {
    asm volatile(
        "mma.sync.aligned.m16n8k16.row.col.f32.bf16.bf16.f32 "
        "{%0,%1,%2,%3}, {%4,%5,%6,%7}, {%8,%9}, {%0,%1,%2,%3};"
        : "+f"(d[0]), "+f"(d[1]), "+f"(d[2]), "+f"(d[3])
        : "r"(a[0]), "r"(a[1]), "r"(a[2]), "r"(a[3]), "r"(b0), "r"(b1));
}

__device__ __forceinline__ uint32_t bfpair(float a, float b) {
    uint32_t r;
    asm("cvt.rn.bf16x2.f32 %0, %1, %2;" : "=r"(r) : "f"(b), "f"(a));
    return r;
}

__device__ __forceinline__ void split_pair(float a, float b,
                                           uint32_t& hi, uint32_t& lo) {
    hi = bfpair(a, b);
    float ah = __uint_as_float(hi << 16);
    float bh = __uint_as_float(hi & 0xFFFF0000u);
    lo = bfpair(a - ah, b - bh);
}

__device__ __forceinline__ void split4(float4 v, uint2& hi, uint2& lo) {
    split_pair(v.x, v.y, hi.x, lo.x);
    split_pair(v.z, v.w, hi.y, lo.y);
}

__device__ __forceinline__ void cp16(uint32_t dst, const void* src) {
    asm volatile("cp.async.ca.shared.global [%0], [%1], 16;"
                 :: "r"(dst), "l"(__cvta_generic_to_global(src)));
}

// ---------------------------------------------------------------------------
// Projection via mma.sync bf16 hi/lo split; epilogue emits pre-split bf16
// (scaled for Q) for sel 0..2, fp32 for sel 3 (final output).
// ---------------------------------------------------------------------------
#define LDA 72
#define SA_HI 0
#define SA_LO (128 * LDA)
#define SB_HI (2 * 128 * LDA)
#define SB_LO (3 * 128 * LDA)
#define PROJ_SMEM (4 * 128 * LDA * 2)

__global__ void __launch_bounds__(256, 1)
proj_mma(const float* __restrict__ Xext, const float* __restrict__ W,
         const float* __restrict__ bias, float* __restrict__ Yext, int sel)
{
    extern __shared__ __nv_bfloat16 sb[];

    const float* X = (sel == 3) ? g_ctx : Xext;

    const int tid = threadIdx.x;
    const int l   = tid & 31;
    const int wid = tid >> 5;
    const int wm  = wid & 3;
    const int wn  = wid >> 2;
    const int row0 = blockIdx.y * 128;
    const int col0 = blockIdx.x * 128;

    float acc[2][8][4];
#pragma unroll
    for (int m = 0; m < 2; ++m)
#pragma unroll
        for (int n = 0; n < 8; ++n)
#pragma unroll
            for (int i = 0; i < 4; ++i) acc[m][n][i] = 0.f;

    const uint32_t a_off_elem =
        (uint32_t)(wm * 32 + (l & 15)) * LDA + ((l >> 4) * 8);
    const uint32_t b_off_elem =
        (uint32_t)(wn * 64 + (l & 7) + ((l >> 4) << 3)) * LDA + (((l >> 3) & 1) * 8);
    const uint32_t smb = smem_u32(sb);

    for (int kb = 0; kb < 4; ++kb) {
#pragma unroll
        for (int i = 0; i < 8; ++i) {
            int t   = tid + i * 256;
            int row = t >> 4;
            int c4  = (t & 15) * 4;
            uint2 hi, lo;
            split4(*(const float4*)&X[(size_t)(row0 + row) * CDIM + kb * 64 + c4], hi, lo);
            *(uint2*)&sb[SA_HI + row * LDA + c4] = hi;
            *(uint2*)&sb[SA_LO + row * LDA + c4] = lo;
            split4(*(const float4*)&W[(size_t)(col0 + row) * CDIM + kb * 64 + c4], hi, lo);
            *(uint2*)&sb[SB_HI + row * LDA + c4] = hi;
            *(uint2*)&sb[SB_LO + row * LDA + c4] = lo;
        }
        __syncthreads();

#pragma unroll
        for (int ks = 0; ks < 4; ++ks) {
            const uint32_t kk = ks * 16;
            uint32_t ahi[2][4], alo[2][4];
#pragma unroll
            for (int m = 0; m < 2; ++m) {
                uint32_t ae = a_off_elem + (uint32_t)m * 16 * LDA + kk;
                ldm_x4(ahi[m], smb + (SA_HI + ae) * 2);
                ldm_x4(alo[m], smb + (SA_LO + ae) * 2);
            }
#pragma unroll
            for (int p = 0; p < 4; ++p) {
                uint32_t be = b_off_elem + (uint32_t)p * 16 * LDA + kk;
                uint32_t bhi[4], blo[4];
                ldm_x4(bhi, smb + (SB_HI + be) * 2);
                ldm_x4(blo, smb + (SB_LO + be) * 2);
#pragma unroll
                for (int m = 0; m < 2; ++m) {
                    mma_bf16(acc[m][2 * p + 0], ahi[m], bhi[0], bhi[1]);
                    mma_bf16(acc[m][2 * p + 0], ahi[m], blo[0], blo[1]);
                    mma_bf16(acc[m][2 * p + 0], alo[m], bhi[0], bhi[1]);
                    mma_bf16(acc[m][2 * p + 1], ahi[m], bhi[2], bhi[3]);
                    mma_bf16(acc[m][2 * p + 1], ahi[m], blo[2], blo[3]);
                    mma_bf16(acc[m][2 * p + 1], alo[m], bhi[2], bhi[3]);
                }
            }
        }
        __syncthreads();
    }

    if (sel < 3) {
        __nv_bfloat16 *Yh, *Yl;
        if      (sel == 0) { Yh = g_qh; Yl = g_ql; }
        else if (sel == 1) { Yh = g_kh; Yl = g_kl; }
        else               { Yh = g_vh; Yl = g_vl; }
        const float sc = (sel == 0) ? QSCALE : 1.f;
#pragma unroll
        for (int m = 0; m < 2; ++m) {
            int r = row0 + wm * 32 + m * 16 + (l >> 2);
#pragma unroll
            for (int n = 0; n < 8; ++n) {
                int c = col0 + wn * 64 + n * 8 + (l & 3) * 2;
                float2 b2 = *(const float2*)&bias[c];
                uint32_t hi, lo;
                split_pair((acc[m][n][0] + b2.x) * sc, (acc[m][n][1] + b2.y) * sc, hi, lo);
                *(uint32_t*)&Yh[(size_t)r * CDIM + c] = hi;
                *(uint32_t*)&Yl[(size_t)r * CDIM + c] = lo;
                split_pair((acc[m][n][2] + b2.x) * sc, (acc[m][n][3] + b2.y) * sc, hi, lo);
                *(uint32_t*)&Yh[(size_t)(r + 8) * CDIM + c] = hi;
                *(uint32_t*)&Yl[(size_t)(r + 8) * CDIM + c] = lo;
            }
        }
    } else {
#pragma unroll
        for (int m = 0; m < 2; ++m) {
            int r = row0 + wm * 32 + m * 16 + (l >> 2);
#pragma unroll
            for (int n = 0; n < 8; ++n) {
                int c = col0 + wn * 64 + n * 8 + (l & 3) * 2;
                float2 b2 = *(const float2*)&bias[c];
                *(float2*)&Yext[(size_t)r * CDIM + c] =
                    make_float2(acc[m][n][0] + b2.x, acc[m][n][1] + b2.y);
                *(float2*)&Yext[(size_t)(r + 8) * CDIM + c] =
                    make_float2(acc[m][n][2] + b2.x, acc[m][n][3] + b2.y);
            }
        }
    }
}

// ---------------------------------------------------------------------------
// Flash attention: pre-split bf16 inputs, cp.async double-buffered K/V,
// ldmatrix.trans for V (no scalar transpose). 8 warps x 16 q-rows = 128 rows.
// ---------------------------------------------------------------------------
#define LDT    40                       // elems; 80B row stride
#define QH_OFF 0
#define QL_OFF (128 * LDT * 2)          // 10240
#define KV_OFF (2 * 128 * LDT * 2)      // 20480
#define ARR    (64 * LDT * 2)           // 5120 per array
#define STG    (4 * ARR)                // kh,kl,vh,vl per stage
#define ATTN_SMEM (KV_OFF + 2 * STG)    // 61440

__global__ void __launch_bounds__(256, 2) attn_mma()
{
    extern __shared__ char smc[];
    const uint32_t smb = smem_u32(smc);
    __nv_bfloat16* sQh = (__nv_bfloat16*)(smc + QH_OFF);
    __nv_bfloat16* sQl = (__nv_bfloat16*)(smc + QL_OFF);

    const int tid = threadIdx.x;
    const int l   = tid & 31;
    const int wm  = tid >> 5;
    const int qt  = blockIdx.x;      // 0..7
    const int h   = blockIdx.y;      // 0..7
    const int win = blockIdx.z;      // 0..15

    const int tok0  = win * SEQ + qt * 128;
    const int ktok0 = win * SEQ;

    // ---- issue cp.async for K/V tile 0 (stage 0) ----
    {
        int row = tid >> 2, ch = tid & 3;
        size_t g = (size_t)(ktok0 + row) * CDIM + h * DK + ch * 8;
        uint32_t dst = smb + KV_OFF + row * (LDT * 2) + ch * 16;
        cp16(dst,           g_kh + g);
        cp16(dst + ARR,     g_kl + g);
        cp16(dst + 2 * ARR, g_vh + g);
        cp16(dst + 3 * ARR, g_vl + g);
        asm volatile("cp.async.commit_group;");
    }

    // ---- stage Q (pre-scaled, pre-split) ----
#pragma unroll
    for (int i = 0; i < 2; ++i) {
        int idx = tid + i * 256;
        int row = idx >> 2, ch = idx & 3;
        size_t g = (size_t)(tok0 + row) * CDIM + h * DK + ch * 8;
        *(uint4*)&sQh[row * LDT + ch * 8] = *(const uint4*)&g_qh[g];
        *(uint4*)&sQl[row * LDT + ch * 8] = *(const uint4*)&g_ql[g];
    }
    __syncthreads();

    // ---- preload Q fragments ----
    uint32_t qh[2][4], ql[2][4];
    {
        uint32_t off = ((uint32_t)(wm * 16 + (l & 15)) * LDT + (l >> 4) * 8) * 2;
#pragma unroll
        for (int kk = 0; kk < 2; ++kk) {
            ldm_x4(qh[kk], smb + QH_OFF + off + kk * 32);
            ldm_x4(ql[kk], smb + QL_OFF + off + kk * 32);
        }
    }

    const uint32_t k_lane =
        ((uint32_t)((l & 7) + ((l >> 4) << 3)) * LDT + ((l >> 3) & 1) * 8) * 2;
    const uint32_t v_lane =
        ((uint32_t)(l & 15) * LDT + (l >> 4) * 8) * 2;

    float m0 = -1e30f, m1 = -1e30f, l0 = 0.f, l1 = 0.f;
    float o[4][4];
#pragma unroll
    for (int n = 0; n < 4; ++n)
#pragma unroll
        for (int i = 0; i < 4; ++i) o[n][i] = 0.f;

    for (int kt = 0; kt < SEQ / 64; ++kt) {
        // prefetch tile kt+1 into the other stage buffer
        if (kt + 1 < SEQ / 64) {
            int row = tid >> 2, ch = tid & 3;
            size_t g = (size_t)(ktok0 + (kt + 1) * 64 + row) * CDIM + h * DK + ch * 8;
            uint32_t dst = smb + KV_OFF + ((kt + 1) & 1) * STG + row * (LDT * 2) + ch * 16;
            cp16(dst,           g_kh + g);
            cp16(dst + ARR,     g_kl + g);
            cp16(dst + 2 * ARR, g_vh + g);
            cp16(dst + 3 * ARR, g_vl + g);
            asm volatile("cp.async.commit_group;");
            asm volatile("cp.async.wait_group 1;");
        } else {
            asm volatile("cp.async.wait_group 0;");
        }
        __syncthreads();

        const uint32_t kb = smb + KV_OFF + (kt & 1) * STG;

        // ---- S = Q K^T (16 x 64 per warp), 3-product split ----
        float s[8][4];
#pragma unroll
        for (int j = 0; j < 8; ++j)
#pragma unroll
            for (int i = 0; i < 4; ++i) s[j][i] = 0.f;

#pragma unroll
        for (int kk = 0; kk < 2; ++kk) {
#pragma unroll
            for (int jp = 0; jp < 4; ++jp) {
                uint32_t koff = k_lane + ((uint32_t)(jp * 16 * LDT + kk * 16)) * 2;
                uint32_t kh[4], kl[4];
                ldm_x4(kh, kb + koff);
                ldm_x4(kl, kb + ARR + koff);
                mma_bf16(s[2 * jp + 0], qh[kk], kh[0], kh[1]);
                mma_bf16(s[2 * jp + 0], qh[kk], kl[0], kl[1]);
                mma_bf16(s[2 * jp + 0], ql[kk], kh[0], kh[1]);
                mma_bf16(s[2 * jp + 1], qh[kk], kh[2], kh[3]);
                mma_bf16(s[2 * jp + 1], qh[kk], kl[2], kl[3]);
                mma_bf16(s[2 * jp + 1], ql[kk], kh[2], kh[3]);
            }
        }

        // ---- online softmax (rows l>>2 and +8; quad reduction) ----
        float mx0 = -1e30f, mx1 = -1e30f;
#pragma unroll
        for (int j = 0; j < 8; ++j) {
            mx0 = fmaxf(mx0, fmaxf(s[j][0], s[j][1]));
            mx1 = fmaxf(mx1, fmaxf(s[j][2], s[j][3]));
        }
        mx0 = fmaxf(mx0, __shfl_xor_sync(0xffffffffu, mx0, 1));
        mx0 = fmaxf(mx0, __shfl_xor_sync(0xffffffffu, mx0, 2));
        mx1 = fmaxf(mx1, __shfl_xor_sync(0xffffffffu, mx1, 1));
        mx1 = fmaxf(mx1, __shfl_xor_sync(0xffffffffu, mx1, 2));

        float mn0 = fmaxf(m0, mx0), mn1 = fmaxf(m1, mx1);
        float c0 = ex2f(m0 - mn0), c1 = ex2f(m1 - mn1);
        m0 = mn0; m1 = mn1;

        float rs0 = 0.f, rs1 = 0.f;
#pragma unroll
        for (int j = 0; j < 8; ++j) {
            s[j][0] = ex2f(s[j][0] - mn0);
            s[j][1] = ex2f(s[j][1] - mn0);
            s[j][2] = ex2f(s[j][2] - mn1);
            s[j][3] = ex2f(s[j][3] - mn1);
            rs0 += s[j][0] + s[j][1];
            rs1 += s[j][2] + s[j][3];
        }
        rs0 += __shfl_xor_sync(0xffffffffu, rs0, 1);
        rs0 += __shfl_xor_sync(0xffffffffu, rs0, 2);
        rs1 += __shfl_xor_sync(0xffffffffu, rs1, 1);
        rs1 += __shfl_xor_sync(0xffffffffu, rs1, 2);

        l0 = l0 * c0 + rs0;
        l1 = l1 * c1 + rs1;
#pragma unroll
        for (int n = 0; n < 4; ++n) {
            o[n][0] *= c0; o[n][1] *= c0;
            o[n][2] *= c1; o[n][3] *= c1;
        }

        // ---- O += P V : P repacked in-register, V via ldmatrix.trans ----
#pragma unroll
        for (int kc = 0; kc < 4; ++kc) {
            uint32_t ph[4], pl[4];
            split_pair(s[2 * kc][0],     s[2 * kc][1],     ph[0], pl[0]);
            split_pair(s[2 * kc][2],     s[2 * kc][3],     ph[1], pl[1]);
            split_pair(s[2 * kc + 1][0], s[2 * kc + 1][1], ph[2], pl[2]);
            split_pair(s[2 * kc + 1][2], s[2 * kc + 1][3], ph[3], pl[3]);
#pragma unroll
            for (int nh = 0; nh < 2; ++nh) {
                uint32_t voff = v_lane + ((uint32_t)(kc * 16 * LDT + nh * 16)) * 2;
                uint32_t vh[4], vl[4];
                ldm_x4t(vh, kb + 2 * ARR + voff);
                ldm_x4t(vl, kb + 3 * ARR + voff);
                mma_bf16(o[2 * nh + 0], ph, vh[0], vh[1]);
                mma_bf16(o[2 * nh + 0], ph, vl[0], vl[1]);
                mma_bf16(o[2 * nh + 0], pl, vh[0], vh[1]);
                mma_bf16(o[2 * nh + 1], ph, vh[2], vh[3]);
                mma_bf16(o[2 * nh + 1], ph, vl[2], vl[3]);
                mma_bf16(o[2 * nh + 1], pl, vh[2], vh[3]);
            }
        }
        __syncthreads();   // all warps done reading stage kt before overwrite
    }

    // ---- epilogue ----
    float inv0 = 1.f / l0, inv1 = 1.f / l1;
    int r_lo = tok0 + wm * 16 + (l >> 2);
    int col  = h * DK + (l & 3) * 2;
#pragma unroll
    for (int n = 0; n < 4; ++n) {
        int c = col + n * 8;
        *(float2*)&g_ctx[(size_t)r_lo * CDIM + c] =
            make_float2(o[n][0] * inv0, o[n][1] * inv0);
        *(float2*)&g_ctx[(size_t)(r_lo + 8) * CDIM + c] =
            make_float2(o[n][2] * inv1, o[n][3] * inv1);
    }
}

// ---------------------------------------------------------------------------
extern "C" void kernel_launch(void* const* d_in, const int* in_sizes, int n_in,
                              void* d_out, int out_size)
{
    const float* q  = (const float*)d_in[0];
    const float* k  = (const float*)d_in[1];
    const float* v  = (const float*)d_in[2];
    const float* Wq = (const float*)d_in[3];
    const float* bq = (const float*)d_in[4];
    const float* Wk = (const float*)d_in[5];
    const float* bk = (const float*)d_in[6];
    const float* Wv = (const float*)d_in[7];
    const float* bv = (const float*)d_in[8];
    const float* Wo = (const float*)d_in[9];
    const float* bo = (const float*)d_in[10];
    float* out = (float*)d_out;

    cudaFuncSetAttribute(proj_mma,
                         cudaFuncAttributeMaxDynamicSharedMemorySize, PROJ_SMEM);
    cudaFuncSetAttribute(attn_mma,
                         cudaFuncAttributeMaxDynamicSharedMemorySize, ATTN_SMEM);

    dim3 pgrid(CDIM / 128, NTOK / 128);

    proj_mma<<<pgrid, 256, PROJ_SMEM>>>(q, Wq, bq, nullptr, 0);
    proj_mma<<<pgrid, 256, PROJ_SMEM>>>(k, Wk, bk, nullptr, 1);
    proj_mma<<<pgrid, 256, PROJ_SMEM>>>(v, Wv, bv, nullptr, 2);

    attn_mma<<<dim3(SEQ / 128, NHEADS, NWIN), 256, ATTN_SMEM>>>();

    proj_mma<<<pgrid, 256, PROJ_SMEM>>>(nullptr, Wo, bo, out, 3);
}

// round 6
// speedup vs baseline: 4.3044x; 1.3740x over previous
#include <cuda_runtime.h>
#include <cuda_bf16.h>
#include <cuda_fp16.h>
#include <cstdint>

#define NTOK   16384      // B*P*K*Hp*W
#define CDIM   256
#define NHEADS 8
#define DK     32
#define SEQ    1024
#define NWIN   16

#define QSCALE (0.17677669529663687f * 1.4426950408889634f)  // 1/sqrt(32)*log2e

// Scratch (alloc-free): Q split fp16 hi/lo (pre-scaled), K/V single fp16, ctx fp32
__device__ __half g_qh[NTOK * CDIM];
__device__ __half g_ql[NTOK * CDIM];
__device__ __half g_kh[NTOK * CDIM];
__device__ __half g_vh[NTOK * CDIM];
__device__ float  g_ctx[NTOK * CDIM];

// ---------------------------------------------------------------------------
// helpers
// ---------------------------------------------------------------------------
__device__ __forceinline__ uint32_t smem_u32(const void* p) {
    uint32_t a;
    asm("{ .reg .u64 t; cvta.to.shared.u64 t, %1; cvt.u32.u64 %0, t; }"
        : "=r"(a) : "l"(p));
    return a;
}

__device__ __forceinline__ float ex2f(float x) {
    float y;
    asm("ex2.approx.ftz.f32 %0, %1;" : "=f"(y) : "f"(x));
    return y;
}

__device__ __forceinline__ void ldm_x4(uint32_t* r, uint32_t addr) {
    asm volatile("ldmatrix.sync.aligned.m8n8.x4.shared.b16 {%0,%1,%2,%3}, [%4];"
                 : "=r"(r[0]), "=r"(r[1]), "=r"(r[2]), "=r"(r[3]) : "r"(addr));
}

__device__ __forceinline__ void ldm_x4t(uint32_t* r, uint32_t addr) {
    asm volatile("ldmatrix.sync.aligned.m8n8.x4.trans.shared.b16 {%0,%1,%2,%3}, [%4];"
                 : "=r"(r[0]), "=r"(r[1]), "=r"(r[2]), "=r"(r[3]) : "r"(addr));
}

__device__ __forceinline__ void mma_bf16(float* d, const uint32_t* a,
                                         uint32_t b0, uint32_t b1) {
    asm volatile(
        "mma.sync.aligned.m16n8k16.row.col.f32.bf16.bf16.f32 "
        "{%0,%1,%2,%3}, {%4,%5,%6,%7}, {%8,%9}, {%0,%1,%2,%3};"
        : "+f"(d[0]), "+f"(d[1]), "+f"(d[2]), "+f"(d[3])
        : "r"(a[0]), "r"(a[1]), "r"(a[2]), "r"(a[3]), "r"(b0), "r"(b1));
}

__device__ __forceinline__ void mma_f16(float* d, const uint32_t* a,
                                        uint32_t b0, uint32_t b1) {
    asm volatile(
        "mma.sync.aligned.m16n8k16.row.col.f32.f16.f16.f32 "
        "{%0,%1,%2,%3}, {%4,%5,%6,%7}, {%8,%9}, {%0,%1,%2,%3};"
        : "+f"(d[0]), "+f"(d[1]), "+f"(d[2]), "+f"(d[3])
        : "r"(a[0]), "r"(a[1]), "r"(a[2]), "r"(a[3]), "r"(b0), "r"(b1));
}

__device__ __forceinline__ uint32_t bfpair(float a, float b) {
    uint32_t r;
    asm("cvt.rn.bf16x2.f32 %0, %1, %2;" : "=r"(r) : "f"(b), "f"(a));
    return r;
}

__device__ __forceinline__ void split_pair(float a, float b,
                                           uint32_t& hi, uint32_t& lo) {
    hi = bfpair(a, b);
    float ah = __uint_as_float(hi << 16);
    float bh = __uint_as_float(hi & 0xFFFF0000u);
    lo = bfpair(a - ah, b - bh);
}

__device__ __forceinline__ void split4(float4 v, uint2& hi, uint2& lo) {
    split_pair(v.x, v.y, hi.x, lo.x);
    split_pair(v.z, v.w, hi.y, lo.y);
}

__device__ __forceinline__ uint32_t h2pair(float a, float b) {
    uint32_t r;
    asm("cvt.rn.f16x2.f32 %0, %1, %2;" : "=r"(r) : "f"(b), "f"(a));
    return r;
}

__device__ __forceinline__ void split_pair_h(float a, float b,
                                             uint32_t& hi, uint32_t& lo) {
    hi = h2pair(a, b);
    __half2 h = *reinterpret_cast<__half2*>(&hi);
    float2 f = __half22float2(h);
    lo = h2pair(a - f.x, b - f.y);
}

__device__ __forceinline__ void cp16(uint32_t dst, const void* src) {
    asm volatile("cp.async.ca.shared.global [%0], [%1], 16;"
                 :: "r"(dst), "l"(__cvta_generic_to_global(src)));
}

// ---------------------------------------------------------------------------
// Projection via mma.sync bf16 hi/lo 3-product (fp32-accurate).
// sel = selBase + blockIdx.z: 0->Q (fp16 split, scaled), 1->K (fp16),
// 2->V (fp16), 3->fp32 out.
// ---------------------------------------------------------------------------
#define LDA 72
#define SA_HI 0
#define SA_LO (128 * LDA)
#define SB_HI (2 * 128 * LDA)
#define SB_LO (3 * 128 * LDA)
#define PROJ_SMEM (4 * 128 * LDA * 2)

__global__ void __launch_bounds__(256, 2)
proj_mma(const float* __restrict__ x0, const float* __restrict__ x1,
         const float* __restrict__ x2,
         const float* __restrict__ w0, const float* __restrict__ w1,
         const float* __restrict__ w2, const float* __restrict__ w3,
         const float* __restrict__ b0, const float* __restrict__ b1,
         const float* __restrict__ b2, const float* __restrict__ b3,
         float* __restrict__ Yext, int selBase)
{
    extern __shared__ __nv_bfloat16 sb[];

    const int sel = selBase + blockIdx.z;
    const float *X, *W, *bias;
    if      (sel == 0) { X = x0;    W = w0; bias = b0; }
    else if (sel == 1) { X = x1;    W = w1; bias = b1; }
    else if (sel == 2) { X = x2;    W = w2; bias = b2; }
    else               { X = g_ctx; W = w3; bias = b3; }

    const int tid = threadIdx.x;
    const int l   = tid & 31;
    const int wid = tid >> 5;
    const int wm  = wid & 3;
    const int wn  = wid >> 2;
    const int row0 = blockIdx.y * 128;
    const int col0 = blockIdx.x * 128;

    float acc[2][8][4];
#pragma unroll
    for (int m = 0; m < 2; ++m)
#pragma unroll
        for (int n = 0; n < 8; ++n)
#pragma unroll
            for (int i = 0; i < 4; ++i) acc[m][n][i] = 0.f;

    const uint32_t a_off_elem =
        (uint32_t)(wm * 32 + (l & 15)) * LDA + ((l >> 4) * 8);
    const uint32_t b_off_elem =
        (uint32_t)(wn * 64 + (l & 7) + ((l >> 4) << 3)) * LDA + (((l >> 3) & 1) * 8);
    const uint32_t smb = smem_u32(sb);

    for (int kb = 0; kb < 4; ++kb) {
#pragma unroll
        for (int i = 0; i < 8; ++i) {
            int t   = tid + i * 256;
            int row = t >> 4;
            int c4  = (t & 15) * 4;
            uint2 hi, lo;
            split4(*(const float4*)&X[(size_t)(row0 + row) * CDIM + kb * 64 + c4], hi, lo);
            *(uint2*)&sb[SA_HI + row * LDA + c4] = hi;
            *(uint2*)&sb[SA_LO + row * LDA + c4] = lo;
            split4(*(const float4*)&W[(size_t)(col0 + row) * CDIM + kb * 64 + c4], hi, lo);
            *(uint2*)&sb[SB_HI + row * LDA + c4] = hi;
            *(uint2*)&sb[SB_LO + row * LDA + c4] = lo;
        }
        __syncthreads();

#pragma unroll
        for (int ks = 0; ks < 4; ++ks) {
            const uint32_t kk = ks * 16;
            uint32_t ahi[2][4], alo[2][4];
#pragma unroll
            for (int m = 0; m < 2; ++m) {
                uint32_t ae = a_off_elem + (uint32_t)m * 16 * LDA + kk;
                ldm_x4(ahi[m], smb + (SA_HI + ae) * 2);
                ldm_x4(alo[m], smb + (SA_LO + ae) * 2);
            }
#pragma unroll
            for (int p = 0; p < 4; ++p) {
                uint32_t be = b_off_elem + (uint32_t)p * 16 * LDA + kk;
                uint32_t bhi[4], blo[4];
                ldm_x4(bhi, smb + (SB_HI + be) * 2);
                ldm_x4(blo, smb + (SB_LO + be) * 2);
#pragma unroll
                for (int m = 0; m < 2; ++m) {
                    mma_bf16(acc[m][2 * p + 0], ahi[m], bhi[0], bhi[1]);
                    mma_bf16(acc[m][2 * p + 0], ahi[m], blo[0], blo[1]);
                    mma_bf16(acc[m][2 * p + 0], alo[m], bhi[0], bhi[1]);
                    mma_bf16(acc[m][2 * p + 1], ahi[m], bhi[2], bhi[3]);
                    mma_bf16(acc[m][2 * p + 1], ahi[m], blo[2], blo[3]);
                    mma_bf16(acc[m][2 * p + 1], alo[m], bhi[2], bhi[3]);
                }
            }
        }
        __syncthreads();
    }

    if (sel == 0) {
#pragma unroll
        for (int m = 0; m < 2; ++m) {
            int r = row0 + wm * 32 + m * 16 + (l >> 2);
#pragma unroll
            for (int n = 0; n < 8; ++n) {
                int c = col0 + wn * 64 + n * 8 + (l & 3) * 2;
                float2 b2 = *(const float2*)&bias[c];
                uint32_t hi, lo;
                split_pair_h((acc[m][n][0] + b2.x) * QSCALE,
                             (acc[m][n][1] + b2.y) * QSCALE, hi, lo);
                *(uint32_t*)&g_qh[(size_t)r * CDIM + c] = hi;
                *(uint32_t*)&g_ql[(size_t)r * CDIM + c] = lo;
                split_pair_h((acc[m][n][2] + b2.x) * QSCALE,
                             (acc[m][n][3] + b2.y) * QSCALE, hi, lo);
                *(uint32_t*)&g_qh[(size_t)(r + 8) * CDIM + c] = hi;
                *(uint32_t*)&g_ql[(size_t)(r + 8) * CDIM + c] = lo;
            }
        }
    } else if (sel < 3) {
        __half* Yh = (sel == 1) ? g_kh : g_vh;
#pragma unroll
        for (int m = 0; m < 2; ++m) {
            int r = row0 + wm * 32 + m * 16 + (l >> 2);
#pragma unroll
            for (int n = 0; n < 8; ++n) {
                int c = col0 + wn * 64 + n * 8 + (l & 3) * 2;
                float2 b2 = *(const float2*)&bias[c];
                *(uint32_t*)&Yh[(size_t)r * CDIM + c] =
                    h2pair(acc[m][n][0] + b2.x, acc[m][n][1] + b2.y);
                *(uint32_t*)&Yh[(size_t)(r + 8) * CDIM + c] =
                    h2pair(acc[m][n][2] + b2.x, acc[m][n][3] + b2.y);
            }
        }
    } else {
#pragma unroll
        for (int m = 0; m < 2; ++m) {
            int r = row0 + wm * 32 + m * 16 + (l >> 2);
#pragma unroll
            for (int n = 0; n < 8; ++n) {
                int c = col0 + wn * 64 + n * 8 + (l & 3) * 2;
                float2 b2 = *(const float2*)&bias[c];
                *(float2*)&Yext[(size_t)r * CDIM + c] =
                    make_float2(acc[m][n][0] + b2.x, acc[m][n][1] + b2.y);
                *(float2*)&Yext[(size_t)(r + 8) * CDIM + c] =
                    make_float2(acc[m][n][2] + b2.x, acc[m][n][3] + b2.y);
            }
        }
    }
}

// ---------------------------------------------------------------------------
// Flash attention, fp16 asymmetric 2-product:
//   S = (qh+ql) . kh      (full-precision Q x fp16-rounded K)
//   O = (ph+pl) . vh      (full-precision P x fp16-rounded V)
// cp.async double-buffered K/V, ldmatrix.trans for V.
// ---------------------------------------------------------------------------
#define LDT    40                       // halves; 80B row stride
#define QH_OFF 0
#define QL_OFF (128 * LDT * 2)          // 10240
#define KV_OFF (2 * 128 * LDT * 2)      // 20480
#define KARR   (64 * LDT * 2)           // 5120
#define STG    (2 * KARR)               // K + V per stage
#define ATTN_SMEM (KV_OFF + 2 * STG)    // 40960

__global__ void __launch_bounds__(256, 2) attn_mma()
{
    extern __shared__ char smc[];
    const uint32_t smb = smem_u32(smc);
    __half* sQh = (__half*)(smc + QH_OFF);
    __half* sQl = (__half*)(smc + QL_OFF);

    const int tid = threadIdx.x;
    const int l   = tid & 31;
    const int wm  = tid >> 5;
    const int qt  = blockIdx.x;      // 0..7
    const int h   = blockIdx.y;      // 0..7
    const int win = blockIdx.z;      // 0..15

    const int tok0  = win * SEQ + qt * 128;
    const int ktok0 = win * SEQ;

    // ---- issue cp.async for K/V tile 0 (stage 0) ----
    {
        int row = tid >> 2, ch = tid & 3;
        size_t g = (size_t)(ktok0 + row) * CDIM + h * DK + ch * 8;
        uint32_t dst = smb + KV_OFF + row * (LDT * 2) + ch * 16;
        cp16(dst,        g_kh + g);
        cp16(dst + KARR, g_vh + g);
        asm volatile("cp.async.commit_group;");
    }

    // ---- stage Q (pre-scaled, pre-split fp16) ----
#pragma unroll
    for (int i = 0; i < 2; ++i) {
        int idx = tid + i * 256;
        int row = idx >> 2, ch = idx & 3;
        size_t g = (size_t)(tok0 + row) * CDIM + h * DK + ch * 8;
        *(uint4*)&sQh[row * LDT + ch * 8] = *(const uint4*)&g_qh[g];
        *(uint4*)&sQl[row * LDT + ch * 8] = *(const uint4*)&g_ql[g];
    }
    __syncthreads();

    // ---- preload Q fragments ----
    uint32_t qh[2][4], ql[2][4];
    {
        uint32_t off = ((uint32_t)(wm * 16 + (l & 15)) * LDT + (l >> 4) * 8) * 2;
#pragma unroll
        for (int kk = 0; kk < 2; ++kk) {
            ldm_x4(qh[kk], smb + QH_OFF + off + kk * 32);
            ldm_x4(ql[kk], smb + QL_OFF + off + kk * 32);
        }
    }

    const uint32_t k_lane =
        ((uint32_t)((l & 7) + ((l >> 4) << 3)) * LDT + ((l >> 3) & 1) * 8) * 2;
    const uint32_t v_lane =
        ((uint32_t)(l & 15) * LDT + (l >> 4) * 8) * 2;

    float m0 = -1e30f, m1 = -1e30f, l0 = 0.f, l1 = 0.f;
    float o[4][4];
#pragma unroll
    for (int n = 0; n < 4; ++n)
#pragma unroll
        for (int i = 0; i < 4; ++i) o[n][i] = 0.f;

    for (int kt = 0; kt < SEQ / 64; ++kt) {
        // prefetch tile kt+1 into the other stage
        if (kt + 1 < SEQ / 64) {
            int row = tid >> 2, ch = tid & 3;
            size_t g = (size_t)(ktok0 + (kt + 1) * 64 + row) * CDIM + h * DK + ch * 8;
            uint32_t dst = smb + KV_OFF + ((kt + 1) & 1) * STG + row * (LDT * 2) + ch * 16;
            cp16(dst,        g_kh + g);
            cp16(dst + KARR, g_vh + g);
            asm volatile("cp.async.commit_group;");
            asm volatile("cp.async.wait_group 1;");
        } else {
            asm volatile("cp.async.wait_group 0;");
        }
        __syncthreads();

        const uint32_t kb = smb + KV_OFF + (kt & 1) * STG;

        // ---- S = Q K^T : 2 products (qh + ql) x kh ----
        float s[8][4];
#pragma unroll
        for (int j = 0; j < 8; ++j)
#pragma unroll
            for (int i = 0; i < 4; ++i) s[j][i] = 0.f;

#pragma unroll
        for (int kk = 0; kk < 2; ++kk) {
#pragma unroll
            for (int jp = 0; jp < 4; ++jp) {
                uint32_t koff = k_lane + ((uint32_t)(jp * 16 * LDT + kk * 16)) * 2;
                uint32_t kh[4];
                ldm_x4(kh, kb + koff);
                mma_f16(s[2 * jp + 0], qh[kk], kh[0], kh[1]);
                mma_f16(s[2 * jp + 0], ql[kk], kh[0], kh[1]);
                mma_f16(s[2 * jp + 1], qh[kk], kh[2], kh[3]);
                mma_f16(s[2 * jp + 1], ql[kk], kh[2], kh[3]);
            }
        }

        // ---- online softmax ----
        float mx0 = -1e30f, mx1 = -1e30f;
#pragma unroll
        for (int j = 0; j < 8; ++j) {
            mx0 = fmaxf(mx0, fmaxf(s[j][0], s[j][1]));
            mx1 = fmaxf(mx1, fmaxf(s[j][2], s[j][3]));
        }
        mx0 = fmaxf(mx0, __shfl_xor_sync(0xffffffffu, mx0, 1));
        mx0 = fmaxf(mx0, __shfl_xor_sync(0xffffffffu, mx0, 2));
        mx1 = fmaxf(mx1, __shfl_xor_sync(0xffffffffu, mx1, 1));
        mx1 = fmaxf(mx1, __shfl_xor_sync(0xffffffffu, mx1, 2));

        float mn0 = fmaxf(m0, mx0), mn1 = fmaxf(m1, mx1);
        float c0 = ex2f(m0 - mn0), c1 = ex2f(m1 - mn1);
        m0 = mn0; m1 = mn1;

        float rs0 = 0.f, rs1 = 0.f;
#pragma unroll
        for (int j = 0; j < 8; ++j) {
            s[j][0] = ex2f(s[j][0] - mn0);
            s[j][1] = ex2f(s[j][1] - mn0);
            s[j][2] = ex2f(s[j][2] - mn1);
            s[j][3] = ex2f(s[j][3] - mn1);
            rs0 += s[j][0] + s[j][1];
            rs1 += s[j][2] + s[j][3];
        }
        rs0 += __shfl_xor_sync(0xffffffffu, rs0, 1);
        rs0 += __shfl_xor_sync(0xffffffffu, rs0, 2);
        rs1 += __shfl_xor_sync(0xffffffffu, rs1, 1);
        rs1 += __shfl_xor_sync(0xffffffffu, rs1, 2);

        l0 = l0 * c0 + rs0;
        l1 = l1 * c1 + rs1;
#pragma unroll
        for (int n = 0; n < 4; ++n) {
            o[n][0] *= c0; o[n][1] *= c0;
            o[n][2] *= c1; o[n][3] *= c1;
        }

        // ---- O += P V : 2 products (ph + pl) x vh, V via ldmatrix.trans ----
#pragma unroll
        for (int kc = 0; kc < 4; ++kc) {
            uint32_t ph[4], pl[4];
            split_pair_h(s[2 * kc][0],     s[2 * kc][1],     ph[0], pl[0]);
            split_pair_h(s[2 * kc][2],     s[2 * kc][3],     ph[1], pl[1]);
            split_pair_h(s[2 * kc + 1][0], s[2 * kc + 1][1], ph[2], pl[2]);
            split_pair_h(s[2 * kc + 1][2], s[2 * kc + 1][3], ph[3], pl[3]);
#pragma unroll
            for (int nh = 0; nh < 2; ++nh) {
                uint32_t voff = v_lane + ((uint32_t)(kc * 16 * LDT + nh * 16)) * 2;
                uint32_t vh[4];
                ldm_x4t(vh, kb + KARR + voff);
                mma_f16(o[2 * nh + 0], ph, vh[0], vh[1]);
                mma_f16(o[2 * nh + 0], pl, vh[0], vh[1]);
                mma_f16(o[2 * nh + 1], ph, vh[2], vh[3]);
                mma_f16(o[2 * nh + 1], pl, vh[2], vh[3]);
            }
        }
        __syncthreads();
    }

    // ---- epilogue ----
    float inv0 = 1.f / l0, inv1 = 1.f / l1;
    int r_lo = tok0 + wm * 16 + (l >> 2);
    int col  = h * DK + (l & 3) * 2;
#pragma unroll
    for (int n = 0; n < 4; ++n) {
        int c = col + n * 8;
        *(float2*)&g_ctx[(size_t)r_lo * CDIM + c] =
            make_float2(o[n][0] * inv0, o[n][1] * inv0);
        *(float2*)&g_ctx[(size_t)(r_lo + 8) * CDIM + c] =
            make_float2(o[n][2] * inv1, o[n][3] * inv1);
    }
}

// ---------------------------------------------------------------------------
extern "C" void kernel_launch(void* const* d_in, const int* in_sizes, int n_in,
                              void* d_out, int out_size)
{
    const float* q  = (const float*)d_in[0];
    const float* k  = (const float*)d_in[1];
    const float* v  = (const float*)d_in[2];
    const float* Wq = (const float*)d_in[3];
    const float* bq = (const float*)d_in[4];
    const float* Wk = (const float*)d_in[5];
    const float* bk = (const float*)d_in[6];
    const float* Wv = (const float*)d_in[7];
    const float* bv = (const float*)d_in[8];
    const float* Wo = (const float*)d_in[9];
    const float* bo = (const float*)d_in[10];
    float* out = (float*)d_out;

    cudaFuncSetAttribute(proj_mma,
                         cudaFuncAttributeMaxDynamicSharedMemorySize, PROJ_SMEM);
    cudaFuncSetAttribute(attn_mma,
                         cudaFuncAttributeMaxDynamicSharedMemorySize, ATTN_SMEM);

    // fused Q/K/V projections: grid.z selects sel
    proj_mma<<<dim3(CDIM / 128, NTOK / 128, 3), 256, PROJ_SMEM>>>(
        q, k, v, Wq, Wk, Wv, Wo, bq, bk, bv, bo, nullptr, 0);

    attn_mma<<<dim3(SEQ / 128, NHEADS, NWIN), 256, ATTN_SMEM>>>();

    proj_mma<<<dim3(CDIM / 128, NTOK / 128, 1), 256, PROJ_SMEM>>>(
        q, k, v, Wq, Wk, Wv, Wo, bq, bk, bv, bo, out, 3);
}

// round 7
// speedup vs baseline: 4.5495x; 1.0569x over previous
#include <cuda_runtime.h>
#include <cuda_fp16.h>
#include <cstdint>

#define NTOK   16384      // B*P*K*Hp*W
#define CDIM   256
#define NHEADS 8
#define DK     32
#define SEQ    1024
#define NWIN   16

#define QSCALE (0.17677669529663687f * 1.4426950408889634f)  // 1/sqrt(32)*log2e

// Scratch (alloc-free)
__device__ __half g_xh[3 * NTOK * CDIM];   // q,k,v inputs split hi
__device__ __half g_xl[3 * NTOK * CDIM];   // q,k,v inputs split lo
__device__ __half g_wh[4 * CDIM * CDIM];   // Wq,Wk,Wv,Wo rounded fp16
__device__ __half g_qh[NTOK * CDIM];       // Q proj, scaled, split hi
__device__ __half g_ql[NTOK * CDIM];       // Q proj, scaled, split lo
__device__ __half g_kh[NTOK * CDIM];       // K proj fp16
__device__ __half g_vh[NTOK * CDIM];       // V proj fp16
__device__ __half g_ch[NTOK * CDIM];       // ctx split hi
__device__ __half g_cl[NTOK * CDIM];       // ctx split lo

// ---------------------------------------------------------------------------
// helpers
// ---------------------------------------------------------------------------
__device__ __forceinline__ uint32_t smem_u32(const void* p) {
    uint32_t a;
    asm("{ .reg .u64 t; cvta.to.shared.u64 t, %1; cvt.u32.u64 %0, t; }"
        : "=r"(a) : "l"(p));
    return a;
}

__device__ __forceinline__ float ex2f(float x) {
    float y;
    asm("ex2.approx.ftz.f32 %0, %1;" : "=f"(y) : "f"(x));
    return y;
}

__device__ __forceinline__ uint32_t swz(uint32_t off) {   // SW128
    return off ^ ((off >> 3) & 0x70);
}

__device__ __forceinline__ void ldm_x4(uint32_t* r, uint32_t addr) {
    asm volatile("ldmatrix.sync.aligned.m8n8.x4.shared.b16 {%0,%1,%2,%3}, [%4];"
                 : "=r"(r[0]), "=r"(r[1]), "=r"(r[2]), "=r"(r[3]) : "r"(addr));
}

__device__ __forceinline__ void ldm_x4t(uint32_t* r, uint32_t addr) {
    asm volatile("ldmatrix.sync.aligned.m8n8.x4.trans.shared.b16 {%0,%1,%2,%3}, [%4];"
                 : "=r"(r[0]), "=r"(r[1]), "=r"(r[2]), "=r"(r[3]) : "r"(addr));
}

__device__ __forceinline__ void mma_f16(float* d, const uint32_t* a,
                                        uint32_t b0, uint32_t b1) {
    asm volatile(
        "mma.sync.aligned.m16n8k16.row.col.f32.f16.f16.f32 "
        "{%0,%1,%2,%3}, {%4,%5,%6,%7}, {%8,%9}, {%0,%1,%2,%3};"
        : "+f"(d[0]), "+f"(d[1]), "+f"(d[2]), "+f"(d[3])
        : "r"(a[0]), "r"(a[1]), "r"(a[2]), "r"(a[3]), "r"(b0), "r"(b1));
}

__device__ __forceinline__ uint32_t h2pair(float a, float b) {
    uint32_t r;
    asm("cvt.rn.f16x2.f32 %0, %1, %2;" : "=r"(r) : "f"(b), "f"(a));
    return r;
}

__device__ __forceinline__ void split_pair_h(float a, float b,
                                             uint32_t& hi, uint32_t& lo) {
    hi = h2pair(a, b);
    __half2 h = *reinterpret_cast<__half2*>(&hi);
    float2 f = __half22float2(h);
    lo = h2pair(a - f.x, b - f.y);
}

__device__ __forceinline__ void split4h(float4 v, uint2& hi, uint2& lo) {
    split_pair_h(v.x, v.y, hi.x, lo.x);
    split_pair_h(v.z, v.w, hi.y, lo.y);
}

__device__ __forceinline__ void cp16(uint32_t dst, const void* src) {
    asm volatile("cp.async.ca.shared.global [%0], [%1], 16;"
                 :: "r"(dst), "l"(__cvta_generic_to_global(src)));
}

// ---------------------------------------------------------------------------
// Elementwise pre-split kernels
// ---------------------------------------------------------------------------
__global__ void __launch_bounds__(256) split_x(
    const float* __restrict__ q, const float* __restrict__ k,
    const float* __restrict__ v)
{
    const int z = blockIdx.y;
    const float* src = (z == 0) ? q : (z == 1) ? k : v;
    size_t i = ((size_t)blockIdx.x * 256 + threadIdx.x) * 4;
    float4 val = *(const float4*)&src[i];
    uint2 hi, lo;
    split4h(val, hi, lo);
    size_t o = (size_t)z * NTOK * CDIM + i;
    *(uint2*)&g_xh[o] = hi;
    *(uint2*)&g_xl[o] = lo;
}

__global__ void __launch_bounds__(256) split_w(
    const float* __restrict__ w0, const float* __restrict__ w1,
    const float* __restrict__ w2, const float* __restrict__ w3)
{
    const int z = blockIdx.y;
    const float* src = (z == 0) ? w0 : (z == 1) ? w1 : (z == 2) ? w2 : w3;
    size_t i = ((size_t)blockIdx.x * 256 + threadIdx.x) * 4;
    float4 v = *(const float4*)&src[i];
    uint2 h;
    h.x = h2pair(v.x, v.y);
    h.y = h2pair(v.z, v.w);
    *(uint2*)&g_wh[(size_t)z * CDIM * CDIM + i] = h;
}

// ---------------------------------------------------------------------------
// Projection: fp16 asymmetric 2-product, cp.async 2-stage pipeline, SW128 smem.
// Y[n][o] = (Xh+Xl)[n][.] . fp16(W)[o][.] + b[o]
// Tile 128(M) x 128(N), K=256 in 4 chunks of 64. 8 warps (4M x 2N).
// sel = selBase + blockIdx.z: 0=Q, 1=K, 2=V (fp16 epilogues), 3=fp32 out.
// ---------------------------------------------------------------------------
#define ASZ  16384              // bytes per 128x64-half swizzled array
#define PSTG (3 * ASZ)          // Ah, Al, Bw
#define PROJ_SMEM (2 * PSTG)    // 98304

__global__ void __launch_bounds__(256, 2)
proj2(const float* __restrict__ b0, const float* __restrict__ b1,
      const float* __restrict__ b2, const float* __restrict__ b3,
      float* __restrict__ Yext, int selBase)
{
    extern __shared__ char sm[];
    const uint32_t smb = smem_u32(sm);

    const int sel = selBase + blockIdx.z;
    const __half *Ah, *Al;
    if (sel < 3) {
        Ah = g_xh + (size_t)sel * NTOK * CDIM;
        Al = g_xl + (size_t)sel * NTOK * CDIM;
    } else {
        Ah = g_ch;
        Al = g_cl;
    }
    const __half* Bw = g_wh + (size_t)sel * CDIM * CDIM;
    const float* bias = (sel == 0) ? b0 : (sel == 1) ? b1 : (sel == 2) ? b2 : b3;

    const int tid = threadIdx.x;
    const int l   = tid & 31;
    const int wid = tid >> 5;
    const int wm  = wid & 3;
    const int wn  = wid >> 2;
    const int row0 = blockIdx.y * 128;
    const int col0 = blockIdx.x * 128;

    auto stage = [&](int kb, int st) {
        const uint32_t sb = smb + st * PSTG;
#pragma unroll
        for (int i = 0; i < 4; ++i) {
            int c   = tid + i * 256;        // 0..1023
            int row = c >> 3;               // 0..127
            int seg = c & 7;                // 16B chunk in row
            uint32_t so = swz((uint32_t)row * 128 + seg * 16);
            size_t ga = (size_t)(row0 + row) * CDIM + kb * 64 + seg * 8;
            cp16(sb + so,           Ah + ga);
            cp16(sb + ASZ + so,     Al + ga);
            cp16(sb + 2 * ASZ + so,
                 Bw + (size_t)(col0 + row) * CDIM + kb * 64 + seg * 8);
        }
        asm volatile("cp.async.commit_group;");
    };

    float acc[2][8][4];
#pragma unroll
    for (int m = 0; m < 2; ++m)
#pragma unroll
        for (int n = 0; n < 8; ++n)
#pragma unroll
            for (int i = 0; i < 4; ++i) acc[m][n][i] = 0.f;

    stage(0, 0);

    for (int kb = 0; kb < 4; ++kb) {
        if (kb + 1 < 4) {
            stage(kb + 1, (kb + 1) & 1);
            asm volatile("cp.async.wait_group 1;");
        } else {
            asm volatile("cp.async.wait_group 0;");
        }
        __syncthreads();

        const uint32_t sb = smb + (kb & 1) * PSTG;

#pragma unroll
        for (int ks = 0; ks < 4; ++ks) {
            const uint32_t colb = ks * 32 + (l >> 4) * 16;   // A col bytes
            uint32_t ahi[2][4], alo[2][4];
#pragma unroll
            for (int m = 0; m < 2; ++m) {
                uint32_t off = swz((uint32_t)(wm * 32 + m * 16 + (l & 15)) * 128 + colb);
                ldm_x4(ahi[m], sb + off);
                ldm_x4(alo[m], sb + ASZ + off);
            }
            const uint32_t bcolb = ks * 32 + ((l >> 3) & 1) * 16;
#pragma unroll
            for (int p = 0; p < 4; ++p) {
                uint32_t boff = swz(
                    (uint32_t)(wn * 64 + p * 16 + (l & 7) + ((l >> 4) << 3)) * 128 + bcolb);
                uint32_t bw[4];
                ldm_x4(bw, sb + 2 * ASZ + boff);
#pragma unroll
                for (int m = 0; m < 2; ++m) {
                    mma_f16(acc[m][2 * p + 0], ahi[m], bw[0], bw[1]);
                    mma_f16(acc[m][2 * p + 0], alo[m], bw[0], bw[1]);
                    mma_f16(acc[m][2 * p + 1], ahi[m], bw[2], bw[3]);
                    mma_f16(acc[m][2 * p + 1], alo[m], bw[2], bw[3]);
                }
            }
        }
        __syncthreads();
    }

    if (sel == 0) {
#pragma unroll
        for (int m = 0; m < 2; ++m) {
            int r = row0 + wm * 32 + m * 16 + (l >> 2);
#pragma unroll
            for (int n = 0; n < 8; ++n) {
                int c = col0 + wn * 64 + n * 8 + (l & 3) * 2;
                float2 b2 = *(const float2*)&bias[c];
                uint32_t hi, lo;
                split_pair_h((acc[m][n][0] + b2.x) * QSCALE,
                             (acc[m][n][1] + b2.y) * QSCALE, hi, lo);
                *(uint32_t*)&g_qh[(size_t)r * CDIM + c] = hi;
                *(uint32_t*)&g_ql[(size_t)r * CDIM + c] = lo;
                split_pair_h((acc[m][n][2] + b2.x) * QSCALE,
                             (acc[m][n][3] + b2.y) * QSCALE, hi, lo);
                *(uint32_t*)&g_qh[(size_t)(r + 8) * CDIM + c] = hi;
                *(uint32_t*)&g_ql[(size_t)(r + 8) * CDIM + c] = lo;
            }
        }
    } else if (sel < 3) {
        __half* Yh = (sel == 1) ? g_kh : g_vh;
#pragma unroll
        for (int m = 0; m < 2; ++m) {
            int r = row0 + wm * 32 + m * 16 + (l >> 2);
#pragma unroll
            for (int n = 0; n < 8; ++n) {
                int c = col0 + wn * 64 + n * 8 + (l & 3) * 2;
                float2 b2 = *(const float2*)&bias[c];
                *(uint32_t*)&Yh[(size_t)r * CDIM + c] =
                    h2pair(acc[m][n][0] + b2.x, acc[m][n][1] + b2.y);
                *(uint32_t*)&Yh[(size_t)(r + 8) * CDIM + c] =
                    h2pair(acc[m][n][2] + b2.x, acc[m][n][3] + b2.y);
            }
        }
    } else {
#pragma unroll
        for (int m = 0; m < 2; ++m) {
            int r = row0 + wm * 32 + m * 16 + (l >> 2);
#pragma unroll
            for (int n = 0; n < 8; ++n) {
                int c = col0 + wn * 64 + n * 8 + (l & 3) * 2;
                float2 b2 = *(const float2*)&bias[c];
                *(float2*)&Yext[(size_t)r * CDIM + c] =
                    make_float2(acc[m][n][0] + b2.x, acc[m][n][1] + b2.y);
                *(float2*)&Yext[(size_t)(r + 8) * CDIM + c] =
                    make_float2(acc[m][n][2] + b2.x, acc[m][n][3] + b2.y);
            }
        }
    }
}

// ---------------------------------------------------------------------------
// Flash attention (unchanged core from R6): fp16 asymmetric 2-product,
// cp.async double-buffered K/V, ldmatrix.trans for V.
// Epilogue now writes ctx pre-split fp16 hi/lo.
// ---------------------------------------------------------------------------
#define LDT    40                       // halves; 80B row stride
#define QH_OFF 0
#define QL_OFF (128 * LDT * 2)
#define KV_OFF (2 * 128 * LDT * 2)
#define KARR   (64 * LDT * 2)
#define STG    (2 * KARR)
#define ATTN_SMEM (KV_OFF + 2 * STG)    // 40960

__global__ void __launch_bounds__(256, 2) attn_mma()
{
    extern __shared__ char smc[];
    const uint32_t smb = smem_u32(smc);
    __half* sQh = (__half*)(smc + QH_OFF);
    __half* sQl = (__half*)(smc + QL_OFF);

    const int tid = threadIdx.x;
    const int l   = tid & 31;
    const int wm  = tid >> 5;
    const int qt  = blockIdx.x;
    const int h   = blockIdx.y;
    const int win = blockIdx.z;

    const int tok0  = win * SEQ + qt * 128;
    const int ktok0 = win * SEQ;

    {
        int row = tid >> 2, ch = tid & 3;
        size_t g = (size_t)(ktok0 + row) * CDIM + h * DK + ch * 8;
        uint32_t dst = smb + KV_OFF + row * (LDT * 2) + ch * 16;
        cp16(dst,        g_kh + g);
        cp16(dst + KARR, g_vh + g);
        asm volatile("cp.async.commit_group;");
    }

#pragma unroll
    for (int i = 0; i < 2; ++i) {
        int idx = tid + i * 256;
        int row = idx >> 2, ch = idx & 3;
        size_t g = (size_t)(tok0 + row) * CDIM + h * DK + ch * 8;
        *(uint4*)&sQh[row * LDT + ch * 8] = *(const uint4*)&g_qh[g];
        *(uint4*)&sQl[row * LDT + ch * 8] = *(const uint4*)&g_ql[g];
    }
    __syncthreads();

    uint32_t qh[2][4], ql[2][4];
    {
        uint32_t off = ((uint32_t)(wm * 16 + (l & 15)) * LDT + (l >> 4) * 8) * 2;
#pragma unroll
        for (int kk = 0; kk < 2; ++kk) {
            ldm_x4(qh[kk], smb + QH_OFF + off + kk * 32);
            ldm_x4(ql[kk], smb + QL_OFF + off + kk * 32);
        }
    }

    const uint32_t k_lane =
        ((uint32_t)((l & 7) + ((l >> 4) << 3)) * LDT + ((l >> 3) & 1) * 8) * 2;
    const uint32_t v_lane =
        ((uint32_t)(l & 15) * LDT + (l >> 4) * 8) * 2;

    float m0 = -1e30f, m1 = -1e30f, l0 = 0.f, l1 = 0.f;
    float o[4][4];
#pragma unroll
    for (int n = 0; n < 4; ++n)
#pragma unroll
        for (int i = 0; i < 4; ++i) o[n][i] = 0.f;

    for (int kt = 0; kt < SEQ / 64; ++kt) {
        if (kt + 1 < SEQ / 64) {
            int row = tid >> 2, ch = tid & 3;
            size_t g = (size_t)(ktok0 + (kt + 1) * 64 + row) * CDIM + h * DK + ch * 8;
            uint32_t dst = smb + KV_OFF + ((kt + 1) & 1) * STG + row * (LDT * 2) + ch * 16;
            cp16(dst,        g_kh + g);
            cp16(dst + KARR, g_vh + g);
            asm volatile("cp.async.commit_group;");
            asm volatile("cp.async.wait_group 1;");
        } else {
            asm volatile("cp.async.wait_group 0;");
        }
        __syncthreads();

        const uint32_t kb = smb + KV_OFF + (kt & 1) * STG;

        float s[8][4];
#pragma unroll
        for (int j = 0; j < 8; ++j)
#pragma unroll
            for (int i = 0; i < 4; ++i) s[j][i] = 0.f;

#pragma unroll
        for (int kk = 0; kk < 2; ++kk) {
#pragma unroll
            for (int jp = 0; jp < 4; ++jp) {
                uint32_t koff = k_lane + ((uint32_t)(jp * 16 * LDT + kk * 16)) * 2;
                uint32_t kh[4];
                ldm_x4(kh, kb + koff);
                mma_f16(s[2 * jp + 0], qh[kk], kh[0], kh[1]);
                mma_f16(s[2 * jp + 0], ql[kk], kh[0], kh[1]);
                mma_f16(s[2 * jp + 1], qh[kk], kh[2], kh[3]);
                mma_f16(s[2 * jp + 1], ql[kk], kh[2], kh[3]);
            }
        }

        float mx0 = -1e30f, mx1 = -1e30f;
#pragma unroll
        for (int j = 0; j < 8; ++j) {
            mx0 = fmaxf(mx0, fmaxf(s[j][0], s[j][1]));
            mx1 = fmaxf(mx1, fmaxf(s[j][2], s[j][3]));
        }
        mx0 = fmaxf(mx0, __shfl_xor_sync(0xffffffffu, mx0, 1));
        mx0 = fmaxf(mx0, __shfl_xor_sync(0xffffffffu, mx0, 2));
        mx1 = fmaxf(mx1, __shfl_xor_sync(0xffffffffu, mx1, 1));
        mx1 = fmaxf(mx1, __shfl_xor_sync(0xffffffffu, mx1, 2));

        float mn0 = fmaxf(m0, mx0), mn1 = fmaxf(m1, mx1);
        float c0 = ex2f(m0 - mn0), c1 = ex2f(m1 - mn1);
        m0 = mn0; m1 = mn1;

        float rs0 = 0.f, rs1 = 0.f;
#pragma unroll
        for (int j = 0; j < 8; ++j) {
            s[j][0] = ex2f(s[j][0] - mn0);
            s[j][1] = ex2f(s[j][1] - mn0);
            s[j][2] = ex2f(s[j][2] - mn1);
            s[j][3] = ex2f(s[j][3] - mn1);
            rs0 += s[j][0] + s[j][1];
            rs1 += s[j][2] + s[j][3];
        }
        rs0 += __shfl_xor_sync(0xffffffffu, rs0, 1);
        rs0 += __shfl_xor_sync(0xffffffffu, rs0, 2);
        rs1 += __shfl_xor_sync(0xffffffffu, rs1, 1);
        rs1 += __shfl_xor_sync(0xffffffffu, rs1, 2);

        l0 = l0 * c0 + rs0;
        l1 = l1 * c1 + rs1;
#pragma unroll
        for (int n = 0; n < 4; ++n) {
            o[n][0] *= c0; o[n][1] *= c0;
            o[n][2] *= c1; o[n][3] *= c1;
        }

#pragma unroll
        for (int kc = 0; kc < 4; ++kc) {
            uint32_t ph[4], pl[4];
            split_pair_h(s[2 * kc][0],     s[2 * kc][1],     ph[0], pl[0]);
            split_pair_h(s[2 * kc][2],     s[2 * kc][3],     ph[1], pl[1]);
            split_pair_h(s[2 * kc + 1][0], s[2 * kc + 1][1], ph[2], pl[2]);
            split_pair_h(s[2 * kc + 1][2], s[2 * kc + 1][3], ph[3], pl[3]);
#pragma unroll
            for (int nh = 0; nh < 2; ++nh) {
                uint32_t voff = v_lane + ((uint32_t)(kc * 16 * LDT + nh * 16)) * 2;
                uint32_t vh[4];
                ldm_x4t(vh, kb + KARR + voff);
                mma_f16(o[2 * nh + 0], ph, vh[0], vh[1]);
                mma_f16(o[2 * nh + 0], pl, vh[0], vh[1]);
                mma_f16(o[2 * nh + 1], ph, vh[2], vh[3]);
                mma_f16(o[2 * nh + 1], pl, vh[2], vh[3]);
            }
        }
        __syncthreads();
    }

    // ---- epilogue: write ctx pre-split fp16 hi/lo ----
    float inv0 = 1.f / l0, inv1 = 1.f / l1;
    int r_lo = tok0 + wm * 16 + (l >> 2);
    int col  = h * DK + (l & 3) * 2;
#pragma unroll
    for (int n = 0; n < 4; ++n) {
        int c = col + n * 8;
        uint32_t hi, lo;
        split_pair_h(o[n][0] * inv0, o[n][1] * inv0, hi, lo);
        *(uint32_t*)&g_ch[(size_t)r_lo * CDIM + c] = hi;
        *(uint32_t*)&g_cl[(size_t)r_lo * CDIM + c] = lo;
        split_pair_h(o[n][2] * inv1, o[n][3] * inv1, hi, lo);
        *(uint32_t*)&g_ch[(size_t)(r_lo + 8) * CDIM + c] = hi;
        *(uint32_t*)&g_cl[(size_t)(r_lo + 8) * CDIM + c] = lo;
    }
}

// ---------------------------------------------------------------------------
extern "C" void kernel_launch(void* const* d_in, const int* in_sizes, int n_in,
                              void* d_out, int out_size)
{
    const float* q  = (const float*)d_in[0];
    const float* k  = (const float*)d_in[1];
    const float* v  = (const float*)d_in[2];
    const float* Wq = (const float*)d_in[3];
    const float* bq = (const float*)d_in[4];
    const float* Wk = (const float*)d_in[5];
    const float* bk = (const float*)d_in[6];
    const float* Wv = (const float*)d_in[7];
    const float* bv = (const float*)d_in[8];
    const float* Wo = (const float*)d_in[9];
    const float* bo = (const float*)d_in[10];
    float* out = (float*)d_out;

    cudaFuncSetAttribute(proj2,
                         cudaFuncAttributeMaxDynamicSharedMemorySize, PROJ_SMEM);
    cudaFuncSetAttribute(attn_mma,
                         cudaFuncAttributeMaxDynamicSharedMemorySize, ATTN_SMEM);

    split_x<<<dim3(NTOK * CDIM / 1024, 3), 256>>>(q, k, v);
    split_w<<<dim3(CDIM * CDIM / 1024, 4), 256>>>(Wq, Wk, Wv, Wo);

    proj2<<<dim3(CDIM / 128, NTOK / 128, 3), 256, PROJ_SMEM>>>(
        bq, bk, bv, bo, nullptr, 0);

    attn_mma<<<dim3(SEQ / 128, NHEADS, NWIN), 256, ATTN_SMEM>>>();

    proj2<<<dim3(CDIM / 128, NTOK / 128, 1), 256, PROJ_SMEM>>>(
        bq, bk, bv, bo, out, 3);
}

// round 8
// speedup vs baseline: 4.5686x; 1.0042x over previous
#include <cuda_runtime.h>
#include <cuda_fp16.h>
#include <cstdint>

#define NTOK   16384      // B*P*K*Hp*W
#define CDIM   256
#define NHEADS 8
#define DK     32
#define SEQ    1024
#define NWIN   16

#define QSCALE (0.17677669529663687f * 1.4426950408889634f)  // 1/sqrt(32)*log2e

// Scratch (alloc-free)
__device__ __half g_x16[3 * NTOK * CDIM];  // q,k,v inputs rounded fp16
__device__ __half g_wh[4 * CDIM * CDIM];   // W split hi
__device__ __half g_wl[4 * CDIM * CDIM];   // W split lo
__device__ __half g_qh[NTOK * CDIM];       // Q proj, scaled, split hi
__device__ __half g_ql[NTOK * CDIM];       // Q proj, scaled, split lo
__device__ __half g_kh[NTOK * CDIM];       // K proj fp16
__device__ __half g_vh[NTOK * CDIM];       // V proj fp16
__device__ __half g_c16[NTOK * CDIM];      // ctx rounded fp16

// ---------------------------------------------------------------------------
// helpers
// ---------------------------------------------------------------------------
__device__ __forceinline__ uint32_t smem_u32(const void* p) {
    uint32_t a;
    asm("{ .reg .u64 t; cvta.to.shared.u64 t, %1; cvt.u32.u64 %0, t; }"
        : "=r"(a) : "l"(p));
    return a;
}

__device__ __forceinline__ float ex2f(float x) {
    float y;
    asm("ex2.approx.ftz.f32 %0, %1;" : "=f"(y) : "f"(x));
    return y;
}

__device__ __forceinline__ uint32_t swz(uint32_t off) {   // SW128
    return off ^ ((off >> 3) & 0x70);
}

__device__ __forceinline__ void ldm_x4(uint32_t* r, uint32_t addr) {
    asm volatile("ldmatrix.sync.aligned.m8n8.x4.shared.b16 {%0,%1,%2,%3}, [%4];"
                 : "=r"(r[0]), "=r"(r[1]), "=r"(r[2]), "=r"(r[3]) : "r"(addr));
}

__device__ __forceinline__ void ldm_x4t(uint32_t* r, uint32_t addr) {
    asm volatile("ldmatrix.sync.aligned.m8n8.x4.trans.shared.b16 {%0,%1,%2,%3}, [%4];"
                 : "=r"(r[0]), "=r"(r[1]), "=r"(r[2]), "=r"(r[3]) : "r"(addr));
}

__device__ __forceinline__ void mma_f16(float* d, const uint32_t* a,
                                        uint32_t b0, uint32_t b1) {
    asm volatile(
        "mma.sync.aligned.m16n8k16.row.col.f32.f16.f16.f32 "
        "{%0,%1,%2,%3}, {%4,%5,%6,%7}, {%8,%9}, {%0,%1,%2,%3};"
        : "+f"(d[0]), "+f"(d[1]), "+f"(d[2]), "+f"(d[3])
        : "r"(a[0]), "r"(a[1]), "r"(a[2]), "r"(a[3]), "r"(b0), "r"(b1));
}

__device__ __forceinline__ uint32_t h2pair(float a, float b) {
    uint32_t r;
    asm("cvt.rn.f16x2.f32 %0, %1, %2;" : "=r"(r) : "f"(b), "f"(a));
    return r;
}

__device__ __forceinline__ void split_pair_h(float a, float b,
                                             uint32_t& hi, uint32_t& lo) {
    hi = h2pair(a, b);
    __half2 h = *reinterpret_cast<__half2*>(&hi);
    float2 f = __half22float2(h);
    lo = h2pair(a - f.x, b - f.y);
}

__device__ __forceinline__ void split4h(float4 v, uint2& hi, uint2& lo) {
    split_pair_h(v.x, v.y, hi.x, lo.x);
    split_pair_h(v.z, v.w, hi.y, lo.y);
}

__device__ __forceinline__ void cp16(uint32_t dst, const void* src) {
    asm volatile("cp.async.ca.shared.global [%0], [%1], 16;"
                 :: "r"(dst), "l"(__cvta_generic_to_global(src)));
}

// ---------------------------------------------------------------------------
// Pre-pass: round x (q,k,v) to fp16; split W exactly into hi/lo fp16.
// ---------------------------------------------------------------------------
__global__ void __launch_bounds__(256) round_x(
    const float* __restrict__ q, const float* __restrict__ k,
    const float* __restrict__ v)
{
    const int z = blockIdx.y;
    const float* src = (z == 0) ? q : (z == 1) ? k : v;
    size_t i = ((size_t)blockIdx.x * 256 + threadIdx.x) * 4;
    float4 val = *(const float4*)&src[i];
    uint2 h;
    h.x = h2pair(val.x, val.y);
    h.y = h2pair(val.z, val.w);
    *(uint2*)&g_x16[(size_t)z * NTOK * CDIM + i] = h;
}

__global__ void __launch_bounds__(256) split_w(
    const float* __restrict__ w0, const float* __restrict__ w1,
    const float* __restrict__ w2, const float* __restrict__ w3)
{
    const int z = blockIdx.y;
    const float* src = (z == 0) ? w0 : (z == 1) ? w1 : (z == 2) ? w2 : w3;
    size_t i = ((size_t)blockIdx.x * 256 + threadIdx.x) * 4;
    float4 v = *(const float4*)&src[i];
    uint2 hi, lo;
    split4h(v, hi, lo);
    size_t o = (size_t)z * CDIM * CDIM + i;
    *(uint2*)&g_wh[o] = hi;
    *(uint2*)&g_wl[o] = lo;
}

// ---------------------------------------------------------------------------
// Projection: Y = x16 . (Wh + Wl) + b  (exact-W, fp16-rounded X), cp.async
// 2-stage pipeline, SW128 smem. Tile 128x128, K in 4 chunks of 64. 8 warps.
// sel = selBase + blockIdx.z: 0=Q (split+scale), 1=K, 2=V (fp16), 3=fp32 out.
// ---------------------------------------------------------------------------
#define ASZ  16384              // bytes per 128x64-half swizzled array
#define PSTG (3 * ASZ)          // A, Bh, Bl
#define PROJ_SMEM (2 * PSTG)    // 98304

__global__ void __launch_bounds__(256, 2)
proj2(const float* __restrict__ b0, const float* __restrict__ b1,
      const float* __restrict__ b2, const float* __restrict__ b3,
      float* __restrict__ Yext, int selBase)
{
    extern __shared__ char sm[];
    const uint32_t smb = smem_u32(sm);

    const int sel = selBase + blockIdx.z;
    const __half* A16 = (sel < 3) ? g_x16 + (size_t)sel * NTOK * CDIM : g_c16;
    const __half* Wh  = g_wh + (size_t)sel * CDIM * CDIM;
    const __half* Wl  = g_wl + (size_t)sel * CDIM * CDIM;
    const float* bias = (sel == 0) ? b0 : (sel == 1) ? b1 : (sel == 2) ? b2 : b3;

    const int tid = threadIdx.x;
    const int l   = tid & 31;
    const int wid = tid >> 5;
    const int wm  = wid & 3;
    const int wn  = wid >> 2;
    const int row0 = blockIdx.y * 128;
    const int col0 = blockIdx.x * 128;

    auto stage = [&](int kb, int st) {
        const uint32_t sb = smb + st * PSTG;
#pragma unroll
        for (int i = 0; i < 4; ++i) {
            int c   = tid + i * 256;        // 0..1023
            int row = c >> 3;               // 0..127
            int seg = c & 7;
            uint32_t so = swz((uint32_t)row * 128 + seg * 16);
            size_t ga = (size_t)(row0 + row) * CDIM + kb * 64 + seg * 8;
            size_t gb = (size_t)(col0 + row) * CDIM + kb * 64 + seg * 8;
            cp16(sb + so,           A16 + ga);
            cp16(sb + ASZ + so,     Wh + gb);
            cp16(sb + 2 * ASZ + so, Wl + gb);
        }
        asm volatile("cp.async.commit_group;");
    };

    float acc[2][8][4];
#pragma unroll
    for (int m = 0; m < 2; ++m)
#pragma unroll
        for (int n = 0; n < 8; ++n)
#pragma unroll
            for (int i = 0; i < 4; ++i) acc[m][n][i] = 0.f;

    stage(0, 0);

    for (int kb = 0; kb < 4; ++kb) {
        if (kb + 1 < 4) {
            stage(kb + 1, (kb + 1) & 1);
            asm volatile("cp.async.wait_group 1;");
        } else {
            asm volatile("cp.async.wait_group 0;");
        }
        __syncthreads();

        const uint32_t sb = smb + (kb & 1) * PSTG;

#pragma unroll
        for (int ks = 0; ks < 4; ++ks) {
            const uint32_t colb = ks * 32 + (l >> 4) * 16;
            uint32_t a16[2][4];
#pragma unroll
            for (int m = 0; m < 2; ++m) {
                uint32_t off = swz((uint32_t)(wm * 32 + m * 16 + (l & 15)) * 128 + colb);
                ldm_x4(a16[m], sb + off);
            }
            const uint32_t bcolb = ks * 32 + ((l >> 3) & 1) * 16;
#pragma unroll
            for (int p = 0; p < 4; ++p) {
                uint32_t boff = swz(
                    (uint32_t)(wn * 64 + p * 16 + (l & 7) + ((l >> 4) << 3)) * 128 + bcolb);
                uint32_t bh[4], bl[4];
                ldm_x4(bh, sb + ASZ + boff);
                ldm_x4(bl, sb + 2 * ASZ + boff);
#pragma unroll
                for (int m = 0; m < 2; ++m) {
                    mma_f16(acc[m][2 * p + 0], a16[m], bh[0], bh[1]);
                    mma_f16(acc[m][2 * p + 0], a16[m], bl[0], bl[1]);
                    mma_f16(acc[m][2 * p + 1], a16[m], bh[2], bh[3]);
                    mma_f16(acc[m][2 * p + 1], a16[m], bl[2], bl[3]);
                }
            }
        }
        __syncthreads();
    }

    if (sel == 0) {
#pragma unroll
        for (int m = 0; m < 2; ++m) {
            int r = row0 + wm * 32 + m * 16 + (l >> 2);
#pragma unroll
            for (int n = 0; n < 8; ++n) {
                int c = col0 + wn * 64 + n * 8 + (l & 3) * 2;
                float2 b2 = *(const float2*)&bias[c];
                uint32_t hi, lo;
                split_pair_h((acc[m][n][0] + b2.x) * QSCALE,
                             (acc[m][n][1] + b2.y) * QSCALE, hi, lo);
                *(uint32_t*)&g_qh[(size_t)r * CDIM + c] = hi;
                *(uint32_t*)&g_ql[(size_t)r * CDIM + c] = lo;
                split_pair_h((acc[m][n][2] + b2.x) * QSCALE,
                             (acc[m][n][3] + b2.y) * QSCALE, hi, lo);
                *(uint32_t*)&g_qh[(size_t)(r + 8) * CDIM + c] = hi;
                *(uint32_t*)&g_ql[(size_t)(r + 8) * CDIM + c] = lo;
            }
        }
    } else if (sel < 3) {
        __half* Yh = (sel == 1) ? g_kh : g_vh;
#pragma unroll
        for (int m = 0; m < 2; ++m) {
            int r = row0 + wm * 32 + m * 16 + (l >> 2);
#pragma unroll
            for (int n = 0; n < 8; ++n) {
                int c = col0 + wn * 64 + n * 8 + (l & 3) * 2;
                float2 b2 = *(const float2*)&bias[c];
                *(uint32_t*)&Yh[(size_t)r * CDIM + c] =
                    h2pair(acc[m][n][0] + b2.x, acc[m][n][1] + b2.y);
                *(uint32_t*)&Yh[(size_t)(r + 8) * CDIM + c] =
                    h2pair(acc[m][n][2] + b2.x, acc[m][n][3] + b2.y);
            }
        }
    } else {
#pragma unroll
        for (int m = 0; m < 2; ++m) {
            int r = row0 + wm * 32 + m * 16 + (l >> 2);
#pragma unroll
            for (int n = 0; n < 8; ++n) {
                int c = col0 + wn * 64 + n * 8 + (l & 3) * 2;
                float2 b2 = *(const float2*)&bias[c];
                *(float2*)&Yext[(size_t)r * CDIM + c] =
                    make_float2(acc[m][n][0] + b2.x, acc[m][n][1] + b2.y);
                *(float2*)&Yext[(size_t)(r + 8) * CDIM + c] =
                    make_float2(acc[m][n][2] + b2.x, acc[m][n][3] + b2.y);
            }
        }
    }
}

// ---------------------------------------------------------------------------
// Flash attention: fp16 asymmetric 2-product, 3-stage cp.async K/V ring,
// ldmatrix.trans for V. Epilogue writes ctx as single fp16.
// ---------------------------------------------------------------------------
#define LDT    40                       // halves; 80B row stride
#define QH_OFF 0
#define QL_OFF (128 * LDT * 2)
#define KV_OFF (2 * 128 * LDT * 2)
#define KARR   (64 * LDT * 2)
#define STG    (2 * KARR)
#define NSTAGE 3
#define ATTN_SMEM (KV_OFF + NSTAGE * STG)   // 51200

__global__ void __launch_bounds__(256, 2) attn_mma()
{
    extern __shared__ char smc[];
    const uint32_t smb = smem_u32(smc);
    __half* sQh = (__half*)(smc + QH_OFF);
    __half* sQl = (__half*)(smc + QL_OFF);

    const int tid = threadIdx.x;
    const int l   = tid & 31;
    const int wm  = tid >> 5;
    const int qt  = blockIdx.x;
    const int h   = blockIdx.y;
    const int win = blockIdx.z;

    const int tok0  = win * SEQ + qt * 128;
    const int ktok0 = win * SEQ;
    const int NT    = SEQ / 64;

    auto issue = [&](int kt) {
        int row = tid >> 2, ch = tid & 3;
        size_t g = (size_t)(ktok0 + kt * 64 + row) * CDIM + h * DK + ch * 8;
        uint32_t dst = smb + KV_OFF + (kt % NSTAGE) * STG + row * (LDT * 2) + ch * 16;
        cp16(dst,        g_kh + g);
        cp16(dst + KARR, g_vh + g);
        asm volatile("cp.async.commit_group;");
    };

    issue(0);
    issue(1);

    // ---- stage Q (pre-scaled, pre-split fp16) ----
#pragma unroll
    for (int i = 0; i < 2; ++i) {
        int idx = tid + i * 256;
        int row = idx >> 2, ch = idx & 3;
        size_t g = (size_t)(tok0 + row) * CDIM + h * DK + ch * 8;
        *(uint4*)&sQh[row * LDT + ch * 8] = *(const uint4*)&g_qh[g];
        *(uint4*)&sQl[row * LDT + ch * 8] = *(const uint4*)&g_ql[g];
    }
    __syncthreads();

    uint32_t qh[2][4], ql[2][4];
    {
        uint32_t off = ((uint32_t)(wm * 16 + (l & 15)) * LDT + (l >> 4) * 8) * 2;
#pragma unroll
        for (int kk = 0; kk < 2; ++kk) {
            ldm_x4(qh[kk], smb + QH_OFF + off + kk * 32);
            ldm_x4(ql[kk], smb + QL_OFF + off + kk * 32);
        }
    }

    const uint32_t k_lane =
        ((uint32_t)((l & 7) + ((l >> 4) << 3)) * LDT + ((l >> 3) & 1) * 8) * 2;
    const uint32_t v_lane =
        ((uint32_t)(l & 15) * LDT + (l >> 4) * 8) * 2;

    float m0 = -1e30f, m1 = -1e30f, l0 = 0.f, l1 = 0.f;
    float o[4][4];
#pragma unroll
    for (int n = 0; n < 4; ++n)
#pragma unroll
        for (int i = 0; i < 4; ++i) o[n][i] = 0.f;

    for (int kt = 0; kt < NT; ++kt) {
        if (kt + 2 < NT) {
            issue(kt + 2);
            asm volatile("cp.async.wait_group 2;");
        } else if (kt + 1 < NT) {
            asm volatile("cp.async.wait_group 1;");
        } else {
            asm volatile("cp.async.wait_group 0;");
        }
        __syncthreads();

        const uint32_t kb = smb + KV_OFF + (kt % NSTAGE) * STG;

        float s[8][4];
#pragma unroll
        for (int j = 0; j < 8; ++j)
#pragma unroll
            for (int i = 0; i < 4; ++i) s[j][i] = 0.f;

#pragma unroll
        for (int kk = 0; kk < 2; ++kk) {
#pragma unroll
            for (int jp = 0; jp < 4; ++jp) {
                uint32_t koff = k_lane + ((uint32_t)(jp * 16 * LDT + kk * 16)) * 2;
                uint32_t kh[4];
                ldm_x4(kh, kb + koff);
                mma_f16(s[2 * jp + 0], qh[kk], kh[0], kh[1]);
                mma_f16(s[2 * jp + 0], ql[kk], kh[0], kh[1]);
                mma_f16(s[2 * jp + 1], qh[kk], kh[2], kh[3]);
                mma_f16(s[2 * jp + 1], ql[kk], kh[2], kh[3]);
            }
        }

        float mx0 = -1e30f, mx1 = -1e30f;
#pragma unroll
        for (int j = 0; j < 8; ++j) {
            mx0 = fmaxf(mx0, fmaxf(s[j][0], s[j][1]));
            mx1 = fmaxf(mx1, fmaxf(s[j][2], s[j][3]));
        }
        mx0 = fmaxf(mx0, __shfl_xor_sync(0xffffffffu, mx0, 1));
        mx0 = fmaxf(mx0, __shfl_xor_sync(0xffffffffu, mx0, 2));
        mx1 = fmaxf(mx1, __shfl_xor_sync(0xffffffffu, mx1, 1));
        mx1 = fmaxf(mx1, __shfl_xor_sync(0xffffffffu, mx1, 2));

        float mn0 = fmaxf(m0, mx0), mn1 = fmaxf(m1, mx1);
        float c0 = ex2f(m0 - mn0), c1 = ex2f(m1 - mn1);
        m0 = mn0; m1 = mn1;

        float rs0 = 0.f, rs1 = 0.f;
#pragma unroll
        for (int j = 0; j < 8; ++j) {
            s[j][0] = ex2f(s[j][0] - mn0);
            s[j][1] = ex2f(s[j][1] - mn0);
            s[j][2] = ex2f(s[j][2] - mn1);
            s[j][3] = ex2f(s[j][3] - mn1);
            rs0 += s[j][0] + s[j][1];
            rs1 += s[j][2] + s[j][3];
        }
        rs0 += __shfl_xor_sync(0xffffffffu, rs0, 1);
        rs0 += __shfl_xor_sync(0xffffffffu, rs0, 2);
        rs1 += __shfl_xor_sync(0xffffffffu, rs1, 1);
        rs1 += __shfl_xor_sync(0xffffffffu, rs1, 2);

        l0 = l0 * c0 + rs0;
        l1 = l1 * c1 + rs1;
#pragma unroll
        for (int n = 0; n < 4; ++n) {
            o[n][0] *= c0; o[n][1] *= c0;
            o[n][2] *= c1; o[n][3] *= c1;
        }

#pragma unroll
        for (int kc = 0; kc < 4; ++kc) {
            uint32_t ph[4], pl[4];
            split_pair_h(s[2 * kc][0],     s[2 * kc][1],     ph[0], pl[0]);
            split_pair_h(s[2 * kc][2],     s[2 * kc][3],     ph[1], pl[1]);
            split_pair_h(s[2 * kc + 1][0], s[2 * kc + 1][1], ph[2], pl[2]);
            split_pair_h(s[2 * kc + 1][2], s[2 * kc + 1][3], ph[3], pl[3]);
#pragma unroll
            for (int nh = 0; nh < 2; ++nh) {
                uint32_t voff = v_lane + ((uint32_t)(kc * 16 * LDT + nh * 16)) * 2;
                uint32_t vh[4];
                ldm_x4t(vh, kb + KARR + voff);
                mma_f16(o[2 * nh + 0], ph, vh[0], vh[1]);
                mma_f16(o[2 * nh + 0], pl, vh[0], vh[1]);
                mma_f16(o[2 * nh + 1], ph, vh[2], vh[3]);
                mma_f16(o[2 * nh + 1], pl, vh[2], vh[3]);
            }
        }
        __syncthreads();
    }

    // ---- epilogue: ctx as single fp16 ----
    float inv0 = 1.f / l0, inv1 = 1.f / l1;
    int r_lo = tok0 + wm * 16 + (l >> 2);
    int col  = h * DK + (l & 3) * 2;
#pragma unroll
    for (int n = 0; n < 4; ++n) {
        int c = col + n * 8;
        *(uint32_t*)&g_c16[(size_t)r_lo * CDIM + c] =
            h2pair(o[n][0] * inv0, o[n][1] * inv0);
        *(uint32_t*)&g_c16[(size_t)(r_lo + 8) * CDIM + c] =
            h2pair(o[n][2] * inv1, o[n][3] * inv1);
    }
}

// ---------------------------------------------------------------------------
extern "C" void kernel_launch(void* const* d_in, const int* in_sizes, int n_in,
                              void* d_out, int out_size)
{
    const float* q  = (const float*)d_in[0];
    const float* k  = (const float*)d_in[1];
    const float* v  = (const float*)d_in[2];
    const float* Wq = (const float*)d_in[3];
    const float* bq = (const float*)d_in[4];
    const float* Wk = (const float*)d_in[5];
    const float* bk = (const float*)d_in[6];
    const float* Wv = (const float*)d_in[7];
    const float* bv = (const float*)d_in[8];
    const float* Wo = (const float*)d_in[9];
    const float* bo = (const float*)d_in[10];
    float* out = (float*)d_out;

    cudaFuncSetAttribute(proj2,
                         cudaFuncAttributeMaxDynamicSharedMemorySize, PROJ_SMEM);
    cudaFuncSetAttribute(attn_mma,
                         cudaFuncAttributeMaxDynamicSharedMemorySize, ATTN_SMEM);

    round_x<<<dim3(NTOK * CDIM / 1024, 3), 256>>>(q, k, v);
    split_w<<<dim3(CDIM * CDIM / 1024, 4), 256>>>(Wq, Wk, Wv, Wo);

    proj2<<<dim3(CDIM / 128, NTOK / 128, 3), 256, PROJ_SMEM>>>(
        bq, bk, bv, bo, nullptr, 0);

    attn_mma<<<dim3(SEQ / 128, NHEADS, NWIN), 256, ATTN_SMEM>>>();

    proj2<<<dim3(CDIM / 128, NTOK / 128, 1), 256, PROJ_SMEM>>>(
        bq, bk, bv, bo, out, 3);
}